// round 4
// baseline (speedup 1.0000x reference)
#include <cuda_runtime.h>
#include <cuda_bf16.h>
#include <cstdint>

// Problem constants
#define NB 4
#define NS 2048
#define NF 512
#define NH 8
#define ND 32
#define HID 256
#define ACTF 16
#define ROWS (NB*NS)          // 8192
#define NP1 896               // padded x-proj output width
#define NPU 520               // action proj width: 256 ku + 256 vu + 8 gamma
#define NC 64                 // chunks per sequence
#define CHUNK 32              // NS / NC
#define EPSF 1e-6f

// ---------------- scratch (static device globals; no allocations) ----------
__device__ __nv_bfloat16 g_Bt1h[NP1*NF];   // [896,512] W1^T hi
__device__ __nv_bfloat16 g_Bt1l[NP1*NF];
__device__ __nv_bfloat16 g_Bt2h[NF*HID];   // [512,256] Wout^T hi
__device__ __nv_bfloat16 g_Bt2l[NF*HID];
__device__ __nv_bfloat16 g_xh[ROWS*NF];    // split x
__device__ __nv_bfloat16 g_xl[ROWS*NF];
__device__ __nv_bfloat16 g_o2h[ROWS*HID];  // split rms output (GEMM2 A)
__device__ __nv_bfloat16 g_o2l[ROWS*HID];
__device__ float g_proj[ROWS*NP1];
__device__ float g_Wucat[ACTF*NPU];
__device__ float g_projU[ROWS*NPU];
__device__ float g_qn[ROWS*HID];
__device__ float g_kn[ROWS*HID];
__device__ float g_kun[ROWS*HID];
__device__ float g_vs[ROWS*HID];
__device__ float g_vu[ROWS*HID];
__device__ float g_sc[ROWS*NH*4];        // beta, Aeff, Bg, ku.k
__device__ float g_u[ROWS*HID];
__device__ float g_w[ROWS*HID];
__device__ float g_cum[32*NC*ND*ND];
__device__ float g_loc[32*NC*ND*ND];
__device__ float g_hinit[32*NC*ND*ND];
__device__ float g_out[ROWS*HID];

__device__ __forceinline__ float sigm(float z) { return 1.f / (1.f + __expf(-z)); }

__device__ __forceinline__ uint32_t smem_to_u32(const void* smem_ptr) {
    uint32_t addr;
    asm("{ .reg .u64 tmp; cvta.to.shared.u64 tmp, %1; cvt.u32.u64 %0, tmp; }"
        : "=r"(addr) : "l"(smem_ptr));
    return addr;
}
__device__ __forceinline__ void ldsm_x4(uint32_t* r, uint32_t addr) {
    asm volatile("ldmatrix.sync.aligned.m8n8.x4.shared.b16 {%0,%1,%2,%3}, [%4];"
        : "=r"(r[0]), "=r"(r[1]), "=r"(r[2]), "=r"(r[3]) : "r"(addr));
}
__device__ __forceinline__ void mma16816(float* d, const uint32_t* a, const uint32_t* b) {
    asm volatile(
        "mma.sync.aligned.m16n8k16.row.col.f32.bf16.bf16.f32 "
        "{%0,%1,%2,%3}, {%4,%5,%6,%7}, {%8,%9}, {%0,%1,%2,%3};"
        : "+f"(d[0]), "+f"(d[1]), "+f"(d[2]), "+f"(d[3])
        : "r"(a[0]), "r"(a[1]), "r"(a[2]), "r"(a[3]), "r"(b[0]), "r"(b[1]));
}
__device__ __forceinline__ void cp16(uint32_t saddr, const void* gaddr) {
    asm volatile("cp.async.cg.shared.global [%0], [%1], 16;" :: "r"(saddr), "l"(gaddr));
}
__device__ __forceinline__ void cp_commit() {
    asm volatile("cp.async.commit_group;" ::: "memory");
}
__device__ __forceinline__ void cp_wait1() {
    asm volatile("cp.async.wait_group 1;" ::: "memory");
}
__device__ __forceinline__ uint32_t pack_bf16(float x, float y) {
    __nv_bfloat16 hx = __float2bfloat16(x), hy = __float2bfloat16(y);
    return ((uint32_t)__bfloat16_as_ushort(hy) << 16) | __bfloat16_as_ushort(hx);
}

// ---------------- 1. weight prep: split-bf16 transposed weights ------------
#define N1ELEM (NP1*NF)
#define N2ELEM (NF*HID)
__global__ void prep_weights(const float* __restrict__ Wq, const float* __restrict__ Wk,
                             const float* __restrict__ Wv, const float* __restrict__ Wb,
                             const float* __restrict__ Wa, const float* __restrict__ Wku,
                             const float* __restrict__ Wvu, const float* __restrict__ Wg,
                             const float* __restrict__ Wout) {
    int i = blockIdx.x * blockDim.x + threadIdx.x;
    if (i < N1ELEM) {
        int n = i >> 9, k = i & 511;          // Bt1[n,k] = W1[k,n]
        float v = 0.f;
        if (n < 256)       v = Wq[k*256 + n];
        else if (n < 512)  v = Wk[k*256 + n - 256];
        else if (n < 768)  v = Wv[k*256 + n - 512];
        else if (n < 776)  v = Wb[k*8 + n - 768];
        else if (n < 784)  v = Wa[k*8 + n - 776];
        __nv_bfloat16 h = __float2bfloat16(v);
        g_Bt1h[i] = h;
        g_Bt1l[i] = __float2bfloat16(v - __bfloat162float(h));
    } else if (i < N1ELEM + N2ELEM) {
        int j = i - N1ELEM;
        int n = j >> 8, k = j & 255;          // Bt2[n,k] = Wout[k,n]
        float v = Wout[k*512 + n];
        __nv_bfloat16 h = __float2bfloat16(v);
        g_Bt2h[j] = h;
        g_Bt2l[j] = __float2bfloat16(v - __bfloat162float(h));
    } else {
        int j = i - N1ELEM - N2ELEM;
        if (j < ACTF * NPU) {
            int r = j / NPU, c = j - r * NPU;
            float v;
            if (c < 256)      v = Wku[r*256 + c];
            else if (c < 512) v = Wvu[r*256 + c - 256];
            else              v = Wg[r*8 + c - 512];
            g_Wucat[j] = v;
        }
    }
}

// ---------------- 1b. split x into hi/lo bf16 -------------------------------
__global__ __launch_bounds__(256) void split_x(const float* __restrict__ x) {
    int i = blockIdx.x * blockDim.x + threadIdx.x;   // float4 index
    float4 v = *(const float4*)(x + i * 4);
    __nv_bfloat16 h0 = __float2bfloat16(v.x), h1 = __float2bfloat16(v.y);
    __nv_bfloat16 h2 = __float2bfloat16(v.z), h3 = __float2bfloat16(v.w);
    uint2 hp, lp;
    hp.x = ((uint32_t)__bfloat16_as_ushort(h1) << 16) | __bfloat16_as_ushort(h0);
    hp.y = ((uint32_t)__bfloat16_as_ushort(h3) << 16) | __bfloat16_as_ushort(h2);
    lp.x = pack_bf16(v.x - __bfloat162float(h0), v.y - __bfloat162float(h1));
    lp.y = pack_bf16(v.z - __bfloat162float(h2), v.w - __bfloat162float(h3));
    *(uint2*)(g_xh + i * 4) = hp;
    *(uint2*)(g_xl + i * 4) = lp;
}

// ---------------- 2. HMMA split-bf16 GEMM, cp.async 3-stage pipeline --------
// C[M,N] = (Ah+Al)[M,K] @ (Bh+Bl)[N,K]^T (drop ll term). Tile 128x128, BK=32.
#define ROWB 80                 // padded smem row stride (bytes)
#define OAH 0
#define OAL 10240
#define OBH 20480
#define OBL 30720
#define STG 40960
#define STAGES 3
#define SMEM_TOTAL (STAGES*STG)

__device__ __forceinline__ void gemm_hmma(const __nv_bfloat16* __restrict__ Ah,
                                          const __nv_bfloat16* __restrict__ Al,
                                          const __nv_bfloat16* __restrict__ Bh,
                                          const __nv_bfloat16* __restrict__ Bl,
                                          float* __restrict__ C,
                                          const float* __restrict__ bias,
                                          int N, int K) {
    extern __shared__ char smem[];
    uint32_t sb = smem_to_u32(smem);
    int tid = threadIdx.x, lane = tid & 31, wid = tid >> 5;
    int m0 = blockIdx.y * 128, n0 = blockIdx.x * 128;
    int wm = (wid >> 2) * 64, wn = (wid & 3) * 32;

    // per-lane ldmatrix byte offsets (16-row x 16-col tiles)
    uint32_t aOff = (uint32_t)((wm + (lane & 7) + ((lane >> 3) & 1) * 8) * ROWB
                               + ((lane >> 4) * 8) * 2);
    uint32_t bOff = (uint32_t)((wn + (lane & 7) + ((lane >> 4) & 1) * 8) * ROWB
                               + (((lane >> 3) & 1) * 8) * 2);

    float acc[4][4][4];
#pragma unroll
    for (int mt = 0; mt < 4; mt++)
#pragma unroll
        for (int nt = 0; nt < 4; nt++)
#pragma unroll
            for (int e = 0; e < 4; e++) acc[mt][nt][e] = 0.f;

    const __nv_bfloat16* Ahg = Ah + (size_t)m0 * K;
    const __nv_bfloat16* Alg = Al + (size_t)m0 * K;
    const __nv_bfloat16* Bhg = Bh + (size_t)n0 * K;
    const __nv_bfloat16* Blg = Bl + (size_t)n0 * K;

    // copy mapping: per array, thread t copies row=t>>1, 32B at seg=(t&1)*32B
    int crow = tid >> 1;
    int cseg = (tid & 1) * 16;      // in bf16 elements (16 bf16 = 32B)
    uint32_t sOff = (uint32_t)(crow * ROWB + cseg * 2);
    int nkc = K >> 5;

#pragma unroll
    for (int ps = 0; ps < STAGES - 1; ps++) {
        uint32_t stb = sb + ps * STG;
        int ko = ps * 32 + cseg;
        const __nv_bfloat16* ga = Ahg + (size_t)crow * K + ko;
        const __nv_bfloat16* gl = Alg + (size_t)crow * K + ko;
        const __nv_bfloat16* gb = Bhg + (size_t)crow * K + ko;
        const __nv_bfloat16* gc = Blg + (size_t)crow * K + ko;
        cp16(stb + OAH + sOff, ga);      cp16(stb + OAH + sOff + 16, ga + 8);
        cp16(stb + OAL + sOff, gl);      cp16(stb + OAL + sOff + 16, gl + 8);
        cp16(stb + OBH + sOff, gb);      cp16(stb + OBH + sOff + 16, gb + 8);
        cp16(stb + OBL + sOff, gc);      cp16(stb + OBL + sOff + 16, gc + 8);
        cp_commit();
    }

    for (int kc = 0; kc < nkc; kc++) {
        cp_wait1();
        __syncthreads();

        // issue loads for stage kc+STAGES-1 (overlaps with compute below)
        int kn = kc + STAGES - 1;
        if (kn < nkc) {
            uint32_t stb = sb + (kn % STAGES) * STG;
            int ko = kn * 32 + cseg;
            const __nv_bfloat16* ga = Ahg + (size_t)crow * K + ko;
            const __nv_bfloat16* gl = Alg + (size_t)crow * K + ko;
            const __nv_bfloat16* gb = Bhg + (size_t)crow * K + ko;
            const __nv_bfloat16* gc = Blg + (size_t)crow * K + ko;
            cp16(stb + OAH + sOff, ga);      cp16(stb + OAH + sOff + 16, ga + 8);
            cp16(stb + OAL + sOff, gl);      cp16(stb + OAL + sOff + 16, gl + 8);
            cp16(stb + OBH + sOff, gb);      cp16(stb + OBH + sOff + 16, gb + 8);
            cp16(stb + OBL + sOff, gc);      cp16(stb + OBL + sOff + 16, gc + 8);
        }
        cp_commit();

        uint32_t stb = sb + (kc % STAGES) * STG;
#pragma unroll
        for (int ks = 0; ks < 2; ks++) {
            uint32_t kb = ks * 32;
            uint32_t af[4][4], bhF[2][4], blF[2][4];
#pragma unroll
            for (int mt = 0; mt < 4; mt++)
                ldsm_x4(af[mt], stb + OAH + aOff + mt * (16 * ROWB) + kb);
#pragma unroll
            for (int np = 0; np < 2; np++) {
                ldsm_x4(bhF[np], stb + OBH + bOff + np * (16 * ROWB) + kb);
                ldsm_x4(blF[np], stb + OBL + bOff + np * (16 * ROWB) + kb);
            }
#pragma unroll
            for (int mt = 0; mt < 4; mt++)
#pragma unroll
                for (int nt = 0; nt < 4; nt++)
                    mma16816(acc[mt][nt], af[mt], &bhF[nt >> 1][(nt & 1) * 2]);
#pragma unroll
            for (int mt = 0; mt < 4; mt++)
#pragma unroll
                for (int nt = 0; nt < 4; nt++)
                    mma16816(acc[mt][nt], af[mt], &blF[nt >> 1][(nt & 1) * 2]);
            // reload A-lo into af, multiply by B-hi
#pragma unroll
            for (int mt = 0; mt < 4; mt++)
                ldsm_x4(af[mt], stb + OAL + aOff + mt * (16 * ROWB) + kb);
#pragma unroll
            for (int mt = 0; mt < 4; mt++)
#pragma unroll
                for (int nt = 0; nt < 4; nt++)
                    mma16816(acc[mt][nt], af[mt], &bhF[nt >> 1][(nt & 1) * 2]);
        }
        __syncthreads();
    }

    // epilogue
#pragma unroll
    for (int mt = 0; mt < 4; mt++) {
        int r0 = m0 + wm + mt * 16 + (lane >> 2);
#pragma unroll
        for (int nt = 0; nt < 4; nt++) {
            int col = n0 + wn + nt * 8 + (lane & 3) * 2;
            float b0 = 0.f, b1 = 0.f;
            if (bias) { b0 = bias[col]; b1 = bias[col + 1]; }
            float2 v0, v1;
            v0.x = acc[mt][nt][0] + b0; v0.y = acc[mt][nt][1] + b1;
            v1.x = acc[mt][nt][2] + b0; v1.y = acc[mt][nt][3] + b1;
            *(float2*)(C + (size_t)r0 * N + col) = v0;
            *(float2*)(C + (size_t)(r0 + 8) * N + col) = v1;
        }
    }
}

__global__ __launch_bounds__(256) void gemm1_tc() {
    gemm_hmma(g_xh, g_xl, g_Bt1h, g_Bt1l, g_proj, nullptr, NP1, NF);
}
__global__ __launch_bounds__(256) void gemm2_tc(const float* __restrict__ bout,
                                                float* __restrict__ y) {
    gemm_hmma(g_o2h, g_o2l, g_Bt2h, g_Bt2l, y, bout, NF, HID);
}

// ---------------- 3. action projection (K=16, tiny) ------------------------
__global__ __launch_bounds__(256) void action_proj(const float* __restrict__ act) {
    __shared__ float a[ACTF];
    int row = blockIdx.x;
    if (threadIdx.x < ACTF) a[threadIdx.x] = act[row * ACTF + threadIdx.x];
    __syncthreads();
    for (int c = threadIdx.x; c < NPU; c += blockDim.x) {
        float s = 0.f;
#pragma unroll
        for (int k = 0; k < ACTF; k++) s += a[k] * g_Wucat[k * NPU + c];
        g_projU[row * NPU + c] = s;
    }
}

// ---------------- 4. activations + l2norm + per-step scalars ----------------
__global__ __launch_bounds__(256) void act_kernel(const float* __restrict__ mask) {
    int w = (blockIdx.x * blockDim.x + threadIdx.x) >> 5;   // (b*S+s)*H + h
    int lane = threadIdx.x & 31;
    if (w >= ROWS * NH) return;
    int bs = w >> 3, h = w & 7;
    int pb = bs * NP1;
    float qr  = g_proj[pb + h*32 + lane];
    float kr  = g_proj[pb + 256 + h*32 + lane];
    float vr  = g_proj[pb + 512 + h*32 + lane];
    float kur = g_projU[bs*NPU + h*32 + lane];
    float vur = g_projU[bs*NPU + 256 + h*32 + lane];

    float q  = qr * sigm(qr);
    float k  = kr * sigm(kr);
    float ku = kur * sigm(kur);

    float sq = q*q, sk = k*k, sku = ku*ku;
#pragma unroll
    for (int o = 16; o > 0; o >>= 1) {
        sq  += __shfl_xor_sync(0xffffffffu, sq,  o);
        sk  += __shfl_xor_sync(0xffffffffu, sk,  o);
        sku += __shfl_xor_sync(0xffffffffu, sku, o);
    }
    q  *= rsqrtf(sq  + EPSF);
    k  *= rsqrtf(sk  + EPSF);
    ku *= rsqrtf(sku + EPSF);

    float dk = ku * k;
#pragma unroll
    for (int o = 16; o > 0; o >>= 1) dk += __shfl_xor_sync(0xffffffffu, dk, o);

    int base = w * 32;
    g_qn[base + lane]  = q;
    g_kn[base + lane]  = k;
    g_kun[base + lane] = ku;
    g_vs[base + lane]  = vr;
    g_vu[base + lane]  = vur;
    if (lane == 0) {
        float br = g_proj[pb + 768 + h];
        float ar = g_proj[pb + 776 + h];
        float gr = g_projU[bs*NPU + 512 + h];
        float m  = mask[bs];
        g_sc[w*4 + 0] = sigm(br);                 // beta
        g_sc[w*4 + 1] = sigm(ar) * (1.f - m);     // Aeff
        g_sc[w*4 + 2] = sigm(gr);                 // Bg
        g_sc[w*4 + 3] = dk;                       // ku . k
    }
}

// ---------------- 5. phase 1: chunked scan (warp per chain-chunk) ----------
__global__ __launch_bounds__(128) void phase1() {
    int wg = blockIdx.x * 4 + (threadIdx.x >> 5);   // 0..2047
    int lane = threadIdx.x & 31;
    int chain = wg >> 6;        // b*8+h
    int c = wg & 63;
    int b = chain >> 3, h = chain & 7;

    float cum[32], hl[32];
#pragma unroll
    for (int j = 0; j < 32; j++) { cum[j] = (j == lane) ? 1.f : 0.f; hl[j] = 0.f; }

    int t0 = c * CHUNK;
    for (int t = t0; t < t0 + CHUNK; t++) {
        int w = (b * NS + t) * NH + h;
        int base = w * 32;
        float kreg  = g_kn[base + lane];
        float qreg  = g_qn[base + lane];
        float kureg = g_kun[base + lane];
        float vs = g_vs[base + lane];
        float vu = g_vu[base + lane];
        float beta = g_sc[w*4 + 0];
        float Ae   = g_sc[w*4 + 1];
        float Bg   = g_sc[w*4 + 2];
        float kuk  = g_sc[w*4 + 3];

        float ck = 0.f, hk = 0.f;
#pragma unroll
        for (int j = 0; j < 32; j++) {
            float kj = __shfl_sync(0xffffffffu, kreg, j);
            ck += cum[j] * kj;
            hk += hl[j]  * kj;
        }
        float e  = Ae * beta * ck;
        float cc = beta * vs - Ae * beta * hk - Bg * beta * kuk * vu;
        float dd = Bg * vu;

        float u = 0.f, wv = 0.f;
#pragma unroll
        for (int j = 0; j < 32; j++) {
            float kj  = __shfl_sync(0xffffffffu, kreg,  j);
            float kuj = __shfl_sync(0xffffffffu, kureg, j);
            float qj  = __shfl_sync(0xffffffffu, qreg,  j);
            cum[j] = Ae * cum[j] - e * kj;
            hl[j]  = Ae * hl[j] + cc * kj + dd * kuj;
            u  += cum[j] * qj;
            wv += hl[j]  * qj;
        }
        g_u[base + lane] = u;
        g_w[base + lane] = wv;
    }
    int mb = (chain * NC + c) * 1024 + lane * 32;
#pragma unroll
    for (int j = 0; j < 32; j += 4) {
        *(float4*)&g_cum[mb + j] = make_float4(cum[j], cum[j+1], cum[j+2], cum[j+3]);
        *(float4*)&g_loc[mb + j] = make_float4(hl[j],  hl[j+1],  hl[j+2],  hl[j+3]);
    }
}

// ---------------- 6. phase 2: fold chunks -----------------------------------
__global__ __launch_bounds__(1024) void phase2(const float* __restrict__ carry,
                                               float* __restrict__ outCarry) {
    int chain = blockIdx.x;
    int i = threadIdx.x >> 5, j = threadIdx.x & 31;
    float hreg = carry[chain * 1024 + i * 32 + j];
    for (int c = 0; c < NC; c++) {
        int mb = (chain * NC + c) * 1024;
        g_hinit[mb + i * 32 + j] = hreg;       // state at chunk start
        float nv = g_loc[mb + i * 32 + j];
#pragma unroll
        for (int m = 0; m < 32; m++)
            nv += __shfl_sync(0xffffffffu, hreg, m) * g_cum[mb + m * 32 + j];
        hreg = nv;
    }
    outCarry[chain * 1024 + i * 32 + j] = hreg;  // new_carry
}

// ---------------- 7. phase 3: out_t = Hinit @ u_t + w_t ---------------------
__global__ __launch_bounds__(256) void phase3() {
    __shared__ float sh[32 * 33];
    int blk = blockIdx.x;            // chain*NC + c
    int chain = blk >> 6, c = blk & 63;
    int b = chain >> 3, h = chain & 7;
    int mb = blk * 1024;
    for (int idx = threadIdx.x; idx < 1024; idx += 256)
        sh[(idx >> 5) * 33 + (idx & 31)] = g_hinit[mb + idx];
    __syncthreads();
    int warp = threadIdx.x >> 5, lane = threadIdx.x & 31;
    for (int it = 0; it < CHUNK / 8; it++) {
        int t = c * CHUNK + it * 8 + warp;
        int w = (b * NS + t) * NH + h;
        int base = w * 32;
        float ul  = g_u[base + lane];
        float acc = g_w[base + lane];
#pragma unroll
        for (int j = 0; j < 32; j++)
            acc += sh[lane * 33 + j] * __shfl_sync(0xffffffffu, ul, j);
        g_out[(b * NS + t) * HID + h * 32 + lane] = acc;
    }
}

// ---------------- 8. RMS norm over 256 + scale -> split bf16 ----------------
__global__ __launch_bounds__(256) void rms_kernel(const float* __restrict__ scale) {
    __shared__ float red[8];
    int bs = blockIdx.x;
    float v = g_out[bs * HID + threadIdx.x];
    float ss = v * v;
#pragma unroll
    for (int o = 16; o > 0; o >>= 1) ss += __shfl_xor_sync(0xffffffffu, ss, o);
    if ((threadIdx.x & 31) == 0) red[threadIdx.x >> 5] = ss;
    __syncthreads();
    float tot = 0.f;
#pragma unroll
    for (int r = 0; r < 8; r++) tot += red[r];
    float inv = rsqrtf(tot * (1.f / 256.f) + EPSF);
    float o = v * inv * scale[threadIdx.x];
    __nv_bfloat16 h = __float2bfloat16(o);
    g_o2h[bs * HID + threadIdx.x] = h;
    g_o2l[bs * HID + threadIdx.x] = __float2bfloat16(o - __bfloat162float(h));
}

// ---------------- launcher ---------------------------------------------------
extern "C" void kernel_launch(void* const* d_in, const int* in_sizes, int n_in,
                              void* d_out, int out_size) {
    const float* x      = (const float*)d_in[0];
    const float* action = (const float*)d_in[1];
    const float* mask   = (const float*)d_in[2];
    const float* carry  = (const float*)d_in[3];
    const float* Wq     = (const float*)d_in[4];
    const float* Wk     = (const float*)d_in[5];
    const float* Wv     = (const float*)d_in[6];
    const float* Wbeta  = (const float*)d_in[7];
    const float* Walpha = (const float*)d_in[8];
    const float* Wku    = (const float*)d_in[9];
    const float* Wvu    = (const float*)d_in[10];
    const float* Wgamma = (const float*)d_in[11];
    const float* rmssc  = (const float*)d_in[12];
    const float* Wout   = (const float*)d_in[13];
    const float* bout   = (const float*)d_in[14];

    float* outCarry = (float*)d_out;                       // (B,H,D,D) = 32768
    float* y        = (float*)d_out + NB * NH * ND * ND;   // (B,S,F)

    cudaFuncSetAttribute(gemm1_tc, cudaFuncAttributeMaxDynamicSharedMemorySize, SMEM_TOTAL);
    cudaFuncSetAttribute(gemm2_tc, cudaFuncAttributeMaxDynamicSharedMemorySize, SMEM_TOTAL);

    int nprep = N1ELEM + N2ELEM + ACTF * NPU;
    prep_weights<<<(nprep + 255) / 256, 256>>>(Wq, Wk, Wv, Wbeta, Walpha, Wku, Wvu,
                                               Wgamma, Wout);
    split_x<<<(ROWS * NF / 4) / 256, 256>>>(x);

    dim3 g1(NP1 / 128, ROWS / 128);       // (7, 64)
    gemm1_tc<<<g1, 256, SMEM_TOTAL>>>();

    action_proj<<<ROWS, 256>>>(action);
    act_kernel<<<(ROWS * NH * 32) / 256, 256>>>(mask);

    phase1<<<512, 128>>>();
    phase2<<<32, 1024>>>(carry, outCarry);
    phase3<<<32 * NC, 256>>>();
    rms_kernel<<<ROWS, 256>>>(rmssc);

    dim3 g2(NF / 128, ROWS / 128);        // (4, 64)
    gemm2_tc<<<g2, 256, SMEM_TOTAL>>>(bout, y);
}

// round 5
// speedup vs baseline: 1.1059x; 1.1059x over previous
#include <cuda_runtime.h>
#include <cuda_bf16.h>
#include <cstdint>

// Problem constants
#define NB 4
#define NS 2048
#define NF 512
#define NH 8
#define ND 32
#define HID 256
#define ACTF 16
#define ROWS (NB*NS)          // 8192
#define NP1 896               // padded x-proj output width
#define NC 32                 // chunks per sequence
#define CHUNK 64              // NS / NC
#define EPSF 1e-6f

// ---------------- scratch (static device globals; no allocations) ----------
__device__ __nv_bfloat16 g_Bt1h[NP1*NF];   // [896,512] W1^T hi
__device__ __nv_bfloat16 g_Bt1l[NP1*NF];
__device__ __nv_bfloat16 g_Bt2h[NF*HID];   // [512,256] Wout^T hi
__device__ __nv_bfloat16 g_Bt2l[NF*HID];
__device__ __nv_bfloat16 g_xh[ROWS*NF];    // split x
__device__ __nv_bfloat16 g_xl[ROWS*NF];
__device__ __nv_bfloat16 g_o2h[ROWS*HID];  // split rms output (GEMM2 A)
__device__ __nv_bfloat16 g_o2l[ROWS*HID];
__device__ float g_proj[ROWS*NP1];
__device__ float g_qn[ROWS*HID];
__device__ float g_kn[ROWS*HID];
__device__ float g_kun[ROWS*HID];
__device__ float g_vs[ROWS*HID];
__device__ float g_vu[ROWS*HID];
__device__ float g_sc[ROWS*NH*4];        // beta, Aeff, Bg, ku.k
__device__ float g_u[ROWS*HID];
__device__ float g_w[ROWS*HID];
__device__ float g_cum[32*NC*ND*ND];
__device__ float g_loc[32*NC*ND*ND];
__device__ float g_hinit[32*NC*ND*ND];
__device__ float g_out[ROWS*HID];

__device__ __forceinline__ float sigm(float z) { return 1.f / (1.f + __expf(-z)); }

__device__ __forceinline__ uint32_t smem_to_u32(const void* smem_ptr) {
    uint32_t addr;
    asm("{ .reg .u64 tmp; cvta.to.shared.u64 tmp, %1; cvt.u32.u64 %0, tmp; }"
        : "=r"(addr) : "l"(smem_ptr));
    return addr;
}
__device__ __forceinline__ void ldsm_x4(uint32_t* r, uint32_t addr) {
    asm volatile("ldmatrix.sync.aligned.m8n8.x4.shared.b16 {%0,%1,%2,%3}, [%4];"
        : "=r"(r[0]), "=r"(r[1]), "=r"(r[2]), "=r"(r[3]) : "r"(addr));
}
__device__ __forceinline__ void mma16816(float* d, const uint32_t* a, const uint32_t* b) {
    asm volatile(
        "mma.sync.aligned.m16n8k16.row.col.f32.bf16.bf16.f32 "
        "{%0,%1,%2,%3}, {%4,%5,%6,%7}, {%8,%9}, {%0,%1,%2,%3};"
        : "+f"(d[0]), "+f"(d[1]), "+f"(d[2]), "+f"(d[3])
        : "r"(a[0]), "r"(a[1]), "r"(a[2]), "r"(a[3]), "r"(b[0]), "r"(b[1]));
}
__device__ __forceinline__ uint32_t pack_bf16(float x, float y) {
    __nv_bfloat16 hx = __float2bfloat16(x), hy = __float2bfloat16(y);
    return ((uint32_t)__bfloat16_as_ushort(hy) << 16) | __bfloat16_as_ushort(hx);
}

// ---------------- 1. weight prep: split-bf16 transposed weights ------------
#define N1ELEM (NP1*NF)
#define N2ELEM (NF*HID)
__global__ void prep_weights(const float* __restrict__ Wq, const float* __restrict__ Wk,
                             const float* __restrict__ Wv, const float* __restrict__ Wb,
                             const float* __restrict__ Wa, const float* __restrict__ Wout) {
    int i = blockIdx.x * blockDim.x + threadIdx.x;
    if (i < N1ELEM) {
        int n = i >> 9, k = i & 511;          // Bt1[n,k] = W1[k,n]
        float v = 0.f;
        if (n < 256)       v = Wq[k*256 + n];
        else if (n < 512)  v = Wk[k*256 + n - 256];
        else if (n < 768)  v = Wv[k*256 + n - 512];
        else if (n < 776)  v = Wb[k*8 + n - 768];
        else if (n < 784)  v = Wa[k*8 + n - 776];
        __nv_bfloat16 h = __float2bfloat16(v);
        g_Bt1h[i] = h;
        g_Bt1l[i] = __float2bfloat16(v - __bfloat162float(h));
    } else if (i < N1ELEM + N2ELEM) {
        int j = i - N1ELEM;
        int n = j >> 8, k = j & 255;          // Bt2[n,k] = Wout[k,n]
        float v = Wout[k*512 + n];
        __nv_bfloat16 h = __float2bfloat16(v);
        g_Bt2h[j] = h;
        g_Bt2l[j] = __float2bfloat16(v - __bfloat162float(h));
    }
}

// ---------------- 1b. split x into hi/lo bf16 -------------------------------
__global__ __launch_bounds__(256) void split_x(const float* __restrict__ x) {
    int i = blockIdx.x * blockDim.x + threadIdx.x;   // float4 index
    float4 v = *(const float4*)(x + i * 4);
    __nv_bfloat16 h0 = __float2bfloat16(v.x), h1 = __float2bfloat16(v.y);
    __nv_bfloat16 h2 = __float2bfloat16(v.z), h3 = __float2bfloat16(v.w);
    uint2 hp, lp;
    hp.x = ((uint32_t)__bfloat16_as_ushort(h1) << 16) | __bfloat16_as_ushort(h0);
    hp.y = ((uint32_t)__bfloat16_as_ushort(h3) << 16) | __bfloat16_as_ushort(h2);
    lp.x = pack_bf16(v.x - __bfloat162float(h0), v.y - __bfloat162float(h1));
    lp.y = pack_bf16(v.z - __bfloat162float(h2), v.w - __bfloat162float(h3));
    *(uint2*)(g_xh + i * 4) = hp;
    *(uint2*)(g_xl + i * 4) = lp;
}

// ---------------- 2. HMMA split-bf16 GEMM, register-staged double buffer ----
// C[M,N] = (Ah+Al)[M,K] @ (Bh+Bl)[N,K]^T (drop ll). Tile 128x128, BK=32.
#define ROWB 80                 // padded smem row stride (bytes)
#define OAH 0
#define OAL 10240
#define OBH 20480
#define OBL 30720
#define STG 40960
#define SMEM_TOTAL (2*STG)

__device__ __forceinline__ void gemm_hmma(const __nv_bfloat16* __restrict__ Ah,
                                          const __nv_bfloat16* __restrict__ Al,
                                          const __nv_bfloat16* __restrict__ Bh,
                                          const __nv_bfloat16* __restrict__ Bl,
                                          float* __restrict__ C,
                                          const float* __restrict__ bias,
                                          int N, int K) {
    extern __shared__ char smem[];
    uint32_t sb = smem_to_u32(smem);
    int tid = threadIdx.x, lane = tid & 31, wid = tid >> 5;
    int m0 = blockIdx.y * 128, n0 = blockIdx.x * 128;
    int wm = (wid >> 2) * 64, wn = (wid & 3) * 32;

    // per-lane ldmatrix byte offsets (16-row x 16-col tiles)
    uint32_t aOff = (uint32_t)((wm + (lane & 7) + ((lane >> 3) & 1) * 8) * ROWB
                               + ((lane >> 4) * 8) * 2);
    uint32_t bOff = (uint32_t)((wn + (lane & 7) + ((lane >> 4) & 1) * 8) * ROWB
                               + (((lane >> 3) & 1) * 8) * 2);

    float acc[4][4][4];
#pragma unroll
    for (int mt = 0; mt < 4; mt++)
#pragma unroll
        for (int nt = 0; nt < 4; nt++)
#pragma unroll
            for (int e = 0; e < 4; e++) acc[mt][nt][e] = 0.f;

    // global copy mapping: per array, thread t -> row = t>>1, 32B at (t&1)*32B
    int crow = tid >> 1;
    int cel = (tid & 1) * 16;                 // element offset (16 bf16 = 32B)
    uint32_t sOff = (uint32_t)(crow * ROWB + (tid & 1) * 32);
    const __nv_bfloat16* pAh = Ah + (size_t)(m0 + crow) * K + cel;
    const __nv_bfloat16* pAl = Al + (size_t)(m0 + crow) * K + cel;
    const __nv_bfloat16* pBh = Bh + (size_t)(n0 + crow) * K + cel;
    const __nv_bfloat16* pBl = Bl + (size_t)(n0 + crow) * K + cel;
    int nkc = K >> 5;

    uint4 rAh[2], rAl[2], rBh[2], rBl[2];
#define LOAD_CHUNK(kc) do {                                             \
        int _ko = (kc) * 32;                                            \
        rAh[0] = *(const uint4*)(pAh + _ko); rAh[1] = *(const uint4*)(pAh + _ko + 8); \
        rAl[0] = *(const uint4*)(pAl + _ko); rAl[1] = *(const uint4*)(pAl + _ko + 8); \
        rBh[0] = *(const uint4*)(pBh + _ko); rBh[1] = *(const uint4*)(pBh + _ko + 8); \
        rBl[0] = *(const uint4*)(pBl + _ko); rBl[1] = *(const uint4*)(pBl + _ko + 8); \
    } while(0)
#define STORE_CHUNK(s) do {                                             \
        char* _st = smem + (s) * STG;                                   \
        *(uint4*)(_st + OAH + sOff) = rAh[0]; *(uint4*)(_st + OAH + sOff + 16) = rAh[1]; \
        *(uint4*)(_st + OAL + sOff) = rAl[0]; *(uint4*)(_st + OAL + sOff + 16) = rAl[1]; \
        *(uint4*)(_st + OBH + sOff) = rBh[0]; *(uint4*)(_st + OBH + sOff + 16) = rBh[1]; \
        *(uint4*)(_st + OBL + sOff) = rBl[0]; *(uint4*)(_st + OBL + sOff + 16) = rBl[1]; \
    } while(0)

    LOAD_CHUNK(0);
    STORE_CHUNK(0);
    __syncthreads();

    for (int kc = 0; kc < nkc; kc++) {
        bool more = (kc + 1 < nkc);
        if (more) LOAD_CHUNK(kc + 1);

        uint32_t stb = sb + (kc & 1) * STG;
#pragma unroll
        for (int ks = 0; ks < 2; ks++) {
            uint32_t kb = ks * 32;
            uint32_t af[4][4], bhF[2][4], blF[2][4];
#pragma unroll
            for (int mt = 0; mt < 4; mt++)
                ldsm_x4(af[mt], stb + OAH + aOff + mt * (16 * ROWB) + kb);
#pragma unroll
            for (int np = 0; np < 2; np++) {
                ldsm_x4(bhF[np], stb + OBH + bOff + np * (16 * ROWB) + kb);
                ldsm_x4(blF[np], stb + OBL + bOff + np * (16 * ROWB) + kb);
            }
#pragma unroll
            for (int mt = 0; mt < 4; mt++)
#pragma unroll
                for (int nt = 0; nt < 4; nt++)
                    mma16816(acc[mt][nt], af[mt], &bhF[nt >> 1][(nt & 1) * 2]);
#pragma unroll
            for (int mt = 0; mt < 4; mt++)
#pragma unroll
                for (int nt = 0; nt < 4; nt++)
                    mma16816(acc[mt][nt], af[mt], &blF[nt >> 1][(nt & 1) * 2]);
            // reload A-lo, multiply by B-hi
#pragma unroll
            for (int mt = 0; mt < 4; mt++)
                ldsm_x4(af[mt], stb + OAL + aOff + mt * (16 * ROWB) + kb);
#pragma unroll
            for (int mt = 0; mt < 4; mt++)
#pragma unroll
                for (int nt = 0; nt < 4; nt++)
                    mma16816(acc[mt][nt], af[mt], &bhF[nt >> 1][(nt & 1) * 2]);
        }
        if (more) {
            __syncthreads();
            STORE_CHUNK((kc + 1) & 1);
            __syncthreads();
        }
    }
#undef LOAD_CHUNK
#undef STORE_CHUNK

    // epilogue
#pragma unroll
    for (int mt = 0; mt < 4; mt++) {
        int r0 = m0 + wm + mt * 16 + (lane >> 2);
#pragma unroll
        for (int nt = 0; nt < 4; nt++) {
            int col = n0 + wn + nt * 8 + (lane & 3) * 2;
            float b0 = 0.f, b1 = 0.f;
            if (bias) { b0 = bias[col]; b1 = bias[col + 1]; }
            float2 v0, v1;
            v0.x = acc[mt][nt][0] + b0; v0.y = acc[mt][nt][1] + b1;
            v1.x = acc[mt][nt][2] + b0; v1.y = acc[mt][nt][3] + b1;
            *(float2*)(C + (size_t)r0 * N + col) = v0;
            *(float2*)(C + (size_t)(r0 + 8) * N + col) = v1;
        }
    }
}

__global__ __launch_bounds__(256) void gemm1_tc() {
    gemm_hmma(g_xh, g_xl, g_Bt1h, g_Bt1l, g_proj, nullptr, NP1, NF);
}
__global__ __launch_bounds__(256) void gemm2_tc(const float* __restrict__ bout,
                                                float* __restrict__ y) {
    gemm_hmma(g_o2h, g_o2l, g_Bt2h, g_Bt2l, y, bout, NF, HID);
}

// ------- 3. activations + l2norm + fused action proj + per-step scalars -----
__global__ __launch_bounds__(256) void act_kernel(const float* __restrict__ mask,
                                                  const float* __restrict__ action,
                                                  const float* __restrict__ Wku,
                                                  const float* __restrict__ Wvu,
                                                  const float* __restrict__ Wg) {
    int w = (blockIdx.x * blockDim.x + threadIdx.x) >> 5;   // (b*S+s)*H + h
    int lane = threadIdx.x & 31;
    if (w >= ROWS * NH) return;
    int bs = w >> 3, h = w & 7;
    int pb = bs * NP1;

    // fused action projection (K=16), weights are L1-resident
    float av = (lane < ACTF) ? action[bs * ACTF + lane] : 0.f;
    float kur = 0.f, vur = 0.f, gr = 0.f;
#pragma unroll
    for (int k2 = 0; k2 < ACTF; k2++) {
        float a = __shfl_sync(0xffffffffu, av, k2);
        kur += a * Wku[k2 * HID + h * 32 + lane];
        vur += a * Wvu[k2 * HID + h * 32 + lane];
        gr  += a * Wg[k2 * NH + h];
    }

    float qr  = g_proj[pb + h*32 + lane];
    float kr  = g_proj[pb + 256 + h*32 + lane];
    float vr  = g_proj[pb + 512 + h*32 + lane];

    float q  = qr * sigm(qr);
    float k  = kr * sigm(kr);
    float ku = kur * sigm(kur);

    float sq = q*q, sk = k*k, sku = ku*ku;
#pragma unroll
    for (int o = 16; o > 0; o >>= 1) {
        sq  += __shfl_xor_sync(0xffffffffu, sq,  o);
        sk  += __shfl_xor_sync(0xffffffffu, sk,  o);
        sku += __shfl_xor_sync(0xffffffffu, sku, o);
    }
    q  *= rsqrtf(sq  + EPSF);
    k  *= rsqrtf(sk  + EPSF);
    ku *= rsqrtf(sku + EPSF);

    float dk = ku * k;
#pragma unroll
    for (int o = 16; o > 0; o >>= 1) dk += __shfl_xor_sync(0xffffffffu, dk, o);

    int base = w * 32;
    g_qn[base + lane]  = q;
    g_kn[base + lane]  = k;
    g_kun[base + lane] = ku;
    g_vs[base + lane]  = vr;
    g_vu[base + lane]  = vur;
    if (lane == 0) {
        float br = g_proj[pb + 768 + h];
        float ar = g_proj[pb + 776 + h];
        float m  = mask[bs];
        g_sc[w*4 + 0] = sigm(br);                 // beta
        g_sc[w*4 + 1] = sigm(ar) * (1.f - m);     // Aeff
        g_sc[w*4 + 2] = sigm(gr);                 // Bg
        g_sc[w*4 + 3] = dk;                       // ku . k
    }
}

// ---------------- 5. phase 1: chunked scan with prefetch --------------------
__global__ __launch_bounds__(128) void phase1() {
    int wg = blockIdx.x * 4 + (threadIdx.x >> 5);   // 0..1023
    int lane = threadIdx.x & 31;
    int chain = wg >> 5;        // b*8+h
    int c = wg & 31;
    int b = chain >> 3, h = chain & 7;

    float cum[32], hl[32];
#pragma unroll
    for (int j = 0; j < 32; j++) { cum[j] = (j == lane) ? 1.f : 0.f; hl[j] = 0.f; }

    int t0 = c * CHUNK;
    int w = (b * NS + t0) * NH + h;
    int base = w * 32;
    float kreg  = g_kn[base + lane];
    float qreg  = g_qn[base + lane];
    float kureg = g_kun[base + lane];
    float vs    = g_vs[base + lane];
    float vu    = g_vu[base + lane];
    float4 scv  = *(const float4*)&g_sc[w * 4];

    for (int t = t0; t < t0 + CHUNK; t++) {
        // prefetch next timestep
        float kN = 0.f, qN = 0.f, kuN = 0.f, vsN = 0.f, vuN = 0.f;
        float4 scN = scv;
        if (t + 1 < t0 + CHUNK) {
            int w2 = (b * NS + t + 1) * NH + h;
            int b2 = w2 * 32;
            kN  = g_kn[b2 + lane];
            qN  = g_qn[b2 + lane];
            kuN = g_kun[b2 + lane];
            vsN = g_vs[b2 + lane];
            vuN = g_vu[b2 + lane];
            scN = *(const float4*)&g_sc[w2 * 4];
        }

        float beta = scv.x, Ae = scv.y, Bg = scv.z, kuk = scv.w;
        float ck = 0.f, hk = 0.f;
#pragma unroll
        for (int j = 0; j < 32; j++) {
            float kj = __shfl_sync(0xffffffffu, kreg, j);
            ck += cum[j] * kj;
            hk += hl[j]  * kj;
        }
        float e  = Ae * beta * ck;
        float cc = beta * vs - Ae * beta * hk - Bg * beta * kuk * vu;
        float dd = Bg * vu;

        float u = 0.f, wv = 0.f;
#pragma unroll
        for (int j = 0; j < 32; j++) {
            float kj  = __shfl_sync(0xffffffffu, kreg,  j);
            float kuj = __shfl_sync(0xffffffffu, kureg, j);
            float qj  = __shfl_sync(0xffffffffu, qreg,  j);
            cum[j] = Ae * cum[j] - e * kj;
            hl[j]  = Ae * hl[j] + cc * kj + dd * kuj;
            u  += cum[j] * qj;
            wv += hl[j]  * qj;
        }
        g_u[base + lane] = u;
        g_w[base + lane] = wv;

        kreg = kN; qreg = qN; kureg = kuN; vs = vsN; vu = vuN; scv = scN;
        base = ((b * NS + t + 1) * NH + h) * 32;
    }
    int mb = (chain * NC + c) * 1024 + lane * 32;
#pragma unroll
    for (int j = 0; j < 32; j += 4) {
        *(float4*)&g_cum[mb + j] = make_float4(cum[j], cum[j+1], cum[j+2], cum[j+3]);
        *(float4*)&g_loc[mb + j] = make_float4(hl[j],  hl[j+1],  hl[j+2],  hl[j+3]);
    }
}

// ---------------- 6. phase 2: fold chunks (smem-staged, prefetched) ---------
__global__ __launch_bounds__(1024) void phase2(const float* __restrict__ carry,
                                               float* __restrict__ outCarry) {
    __shared__ float cumS[2][1024];
    int chain = blockIdx.x;
    int tid = threadIdx.x;
    int i = tid >> 5, j = tid & 31;
    float hreg = carry[chain * 1024 + tid];

    int mb0 = (chain * NC) * 1024;
    float cumNext = g_cum[mb0 + tid];
    float locNext = g_loc[mb0 + tid];

    for (int c = 0; c < NC; c++) {
        int s = c & 1;
        cumS[s][tid] = cumNext;
        float locCur = locNext;
        __syncthreads();
        if (c + 1 < NC) {
            int mb1 = (chain * NC + c + 1) * 1024;
            cumNext = g_cum[mb1 + tid];
            locNext = g_loc[mb1 + tid];
        }
        g_hinit[(chain * NC + c) * 1024 + tid] = hreg;   // state at chunk start
        float nv = locCur;
#pragma unroll
        for (int m = 0; m < 32; m++)
            nv += __shfl_sync(0xffffffffu, hreg, m) * cumS[s][m * 32 + j];
        hreg = nv;
    }
    outCarry[chain * 1024 + tid] = hreg;  // new_carry
}

// ---------------- 7. phase 3: out_t = Hinit @ u_t + w_t ---------------------
__global__ __launch_bounds__(256) void phase3() {
    __shared__ float sh[32 * 33];
    int blk = blockIdx.x;            // chain*NC + c
    int chain = blk >> 5, c = blk & 31;
    int b = chain >> 3, h = chain & 7;
    int mb = blk * 1024;
    for (int idx = threadIdx.x; idx < 1024; idx += 256)
        sh[(idx >> 5) * 33 + (idx & 31)] = g_hinit[mb + idx];
    __syncthreads();
    int warp = threadIdx.x >> 5, lane = threadIdx.x & 31;
    for (int it = 0; it < 8; it++) {
        int t = c * CHUNK + it * 8 + warp;
        int w = (b * NS + t) * NH + h;
        int base = w * 32;
        float ul  = g_u[base + lane];
        float acc = g_w[base + lane];
#pragma unroll
        for (int j = 0; j < 32; j++)
            acc += sh[lane * 33 + j] * __shfl_sync(0xffffffffu, ul, j);
        g_out[(b * NS + t) * HID + h * 32 + lane] = acc;
    }
}

// ---------------- 8. RMS norm over 256 + scale -> split bf16 ----------------
__global__ __launch_bounds__(256) void rms_kernel(const float* __restrict__ scale) {
    __shared__ float red[8];
    int bs = blockIdx.x;
    float v = g_out[bs * HID + threadIdx.x];
    float ss = v * v;
#pragma unroll
    for (int o = 16; o > 0; o >>= 1) ss += __shfl_xor_sync(0xffffffffu, ss, o);
    if ((threadIdx.x & 31) == 0) red[threadIdx.x >> 5] = ss;
    __syncthreads();
    float tot = 0.f;
#pragma unroll
    for (int r = 0; r < 8; r++) tot += red[r];
    float inv = rsqrtf(tot * (1.f / 256.f) + EPSF);
    float o = v * inv * scale[threadIdx.x];
    __nv_bfloat16 hv = __float2bfloat16(o);
    g_o2h[bs * HID + threadIdx.x] = hv;
    g_o2l[bs * HID + threadIdx.x] = __float2bfloat16(o - __bfloat162float(hv));
}

// ---------------- launcher ---------------------------------------------------
extern "C" void kernel_launch(void* const* d_in, const int* in_sizes, int n_in,
                              void* d_out, int out_size) {
    const float* x      = (const float*)d_in[0];
    const float* action = (const float*)d_in[1];
    const float* mask   = (const float*)d_in[2];
    const float* carry  = (const float*)d_in[3];
    const float* Wq     = (const float*)d_in[4];
    const float* Wk     = (const float*)d_in[5];
    const float* Wv     = (const float*)d_in[6];
    const float* Wbeta  = (const float*)d_in[7];
    const float* Walpha = (const float*)d_in[8];
    const float* Wku    = (const float*)d_in[9];
    const float* Wvu    = (const float*)d_in[10];
    const float* Wgamma = (const float*)d_in[11];
    const float* rmssc  = (const float*)d_in[12];
    const float* Wout   = (const float*)d_in[13];
    const float* bout   = (const float*)d_in[14];

    float* outCarry = (float*)d_out;                       // (B,H,D,D) = 32768
    float* y        = (float*)d_out + NB * NH * ND * ND;   // (B,S,F)

    cudaFuncSetAttribute(gemm1_tc, cudaFuncAttributeMaxDynamicSharedMemorySize, SMEM_TOTAL);
    cudaFuncSetAttribute(gemm2_tc, cudaFuncAttributeMaxDynamicSharedMemorySize, SMEM_TOTAL);

    int nprep = N1ELEM + N2ELEM;
    prep_weights<<<(nprep + 255) / 256, 256>>>(Wq, Wk, Wv, Wbeta, Walpha, Wout);
    split_x<<<(ROWS * NF / 4) / 256, 256>>>(x);

    dim3 g1(NP1 / 128, ROWS / 128);       // (7, 64)
    gemm1_tc<<<g1, 256, SMEM_TOTAL>>>();

    act_kernel<<<(ROWS * NH * 32) / 256, 256>>>(mask, action, Wku, Wvu, Wgamma);

    phase1<<<256, 128>>>();
    phase2<<<32, 1024>>>(carry, outCarry);
    phase3<<<32 * NC, 256>>>();
    rms_kernel<<<ROWS, 256>>>(rmssc);

    dim3 g2(NF / 128, ROWS / 128);        // (4, 64)
    gemm2_tc<<<g2, 256, SMEM_TOTAL>>>(bout, y);
}

// round 6
// speedup vs baseline: 1.1106x; 1.0042x over previous
#include <cuda_runtime.h>
#include <cuda_bf16.h>
#include <cstdint>

// Problem constants
#define NB 4
#define NS 2048
#define NF 512
#define NH 8
#define ND 32
#define HID 256
#define ACTF 16
#define ROWS (NB*NS)          // 8192
#define NP1 896               // padded x-proj output width
#define NC 32                 // chunks per sequence
#define CHUNK 64              // NS / NC
#define EPSF 1e-6f

// ---------------- scratch (static device globals; no allocations) ----------
__device__ __nv_bfloat16 g_Bt1h[NP1*NF];   // [896,512] W1^T hi
__device__ __nv_bfloat16 g_Bt1l[NP1*NF];
__device__ __nv_bfloat16 g_Bt2h[NF*HID];   // [512,256] Wout^T hi
__device__ __nv_bfloat16 g_Bt2l[NF*HID];
__device__ __nv_bfloat16 g_xh[ROWS*NF];    // split x
__device__ __nv_bfloat16 g_xl[ROWS*NF];
__device__ __nv_bfloat16 g_o2h[ROWS*HID];  // split rms output (GEMM2 A)
__device__ __nv_bfloat16 g_o2l[ROWS*HID];
__device__ float g_WkuT[HID*ACTF];         // transposed action weights
__device__ float g_WvuT[HID*ACTF];
__device__ float g_WgT[NH*ACTF];
__device__ float g_proj[ROWS*NP1];
__device__ float g_qn[ROWS*HID];
__device__ float g_kn[ROWS*HID];
__device__ float g_kun[ROWS*HID];
__device__ float g_vs[ROWS*HID];
__device__ float g_vu[ROWS*HID];
__device__ float g_sc[ROWS*NH*4];        // beta, Aeff, Bg, ku.k
__device__ float g_u[ROWS*HID];
__device__ float g_w[ROWS*HID];
__device__ float g_cum[32*NC*ND*ND];
__device__ float g_loc[32*NC*ND*ND];
__device__ float g_hinit[32*NC*ND*ND];

__device__ __forceinline__ float sigm(float z) { return 1.f / (1.f + __expf(-z)); }

__device__ __forceinline__ uint32_t smem_to_u32(const void* smem_ptr) {
    uint32_t addr;
    asm("{ .reg .u64 tmp; cvta.to.shared.u64 tmp, %1; cvt.u32.u64 %0, tmp; }"
        : "=r"(addr) : "l"(smem_ptr));
    return addr;
}
__device__ __forceinline__ void ldsm_x4(uint32_t* r, uint32_t addr) {
    asm volatile("ldmatrix.sync.aligned.m8n8.x4.shared.b16 {%0,%1,%2,%3}, [%4];"
        : "=r"(r[0]), "=r"(r[1]), "=r"(r[2]), "=r"(r[3]) : "r"(addr));
}
__device__ __forceinline__ void mma16816(float* d, const uint32_t* a, const uint32_t* b) {
    asm volatile(
        "mma.sync.aligned.m16n8k16.row.col.f32.bf16.bf16.f32 "
        "{%0,%1,%2,%3}, {%4,%5,%6,%7}, {%8,%9}, {%0,%1,%2,%3};"
        : "+f"(d[0]), "+f"(d[1]), "+f"(d[2]), "+f"(d[3])
        : "r"(a[0]), "r"(a[1]), "r"(a[2]), "r"(a[3]), "r"(b[0]), "r"(b[1]));
}
__device__ __forceinline__ void cp16(uint32_t saddr, const void* gaddr) {
    asm volatile("cp.async.cg.shared.global [%0], [%1], 16;" :: "r"(saddr), "l"(gaddr));
}
__device__ __forceinline__ void cp_commit() {
    asm volatile("cp.async.commit_group;" ::: "memory");
}
__device__ __forceinline__ void cp_wait0() {
    asm volatile("cp.async.wait_group 0;" ::: "memory");
}
__device__ __forceinline__ uint32_t pack_bf16(float x, float y) {
    __nv_bfloat16 hx = __float2bfloat16(x), hy = __float2bfloat16(y);
    return ((uint32_t)__bfloat16_as_ushort(hy) << 16) | __bfloat16_as_ushort(hx);
}

// ---------------- 1. weight prep ---------------------------------------------
#define N1ELEM (NP1*NF)
#define N2ELEM (NF*HID)
#define N3ELEM (HID*ACTF)
__global__ void prep_weights(const float* __restrict__ Wq, const float* __restrict__ Wk,
                             const float* __restrict__ Wv, const float* __restrict__ Wb,
                             const float* __restrict__ Wa, const float* __restrict__ Wout,
                             const float* __restrict__ Wku, const float* __restrict__ Wvu,
                             const float* __restrict__ Wg) {
    int i = blockIdx.x * blockDim.x + threadIdx.x;
    if (i < N1ELEM) {
        int n = i >> 9, k = i & 511;          // Bt1[n,k] = W1[k,n]
        float v = 0.f;
        if (n < 256)       v = Wq[k*256 + n];
        else if (n < 512)  v = Wk[k*256 + n - 256];
        else if (n < 768)  v = Wv[k*256 + n - 512];
        else if (n < 776)  v = Wb[k*8 + n - 768];
        else if (n < 784)  v = Wa[k*8 + n - 776];
        __nv_bfloat16 h = __float2bfloat16(v);
        g_Bt1h[i] = h;
        g_Bt1l[i] = __float2bfloat16(v - __bfloat162float(h));
    } else if (i < N1ELEM + N2ELEM) {
        int j = i - N1ELEM;
        int n = j >> 8, k = j & 255;          // Bt2[n,k] = Wout[k,n]
        float v = Wout[k*512 + n];
        __nv_bfloat16 h = __float2bfloat16(v);
        g_Bt2h[j] = h;
        g_Bt2l[j] = __float2bfloat16(v - __bfloat162float(h));
    } else if (i < N1ELEM + N2ELEM + N3ELEM) {
        int j = i - N1ELEM - N2ELEM;
        int c = j >> 4, k = j & 15;
        g_WkuT[j] = Wku[k*HID + c];
        g_WvuT[j] = Wvu[k*HID + c];
    } else if (i < N1ELEM + N2ELEM + N3ELEM + NH*ACTF) {
        int j = i - N1ELEM - N2ELEM - N3ELEM;
        int h = j >> 4, k = j & 15;
        g_WgT[j] = Wg[k*NH + h];
    }
}

// ---------------- 1b. split x into hi/lo bf16 -------------------------------
__global__ __launch_bounds__(256) void split_x(const float* __restrict__ x) {
    int i = blockIdx.x * blockDim.x + threadIdx.x;   // float4 index
    float4 v = *(const float4*)(x + i * 4);
    __nv_bfloat16 h0 = __float2bfloat16(v.x), h1 = __float2bfloat16(v.y);
    __nv_bfloat16 h2 = __float2bfloat16(v.z), h3 = __float2bfloat16(v.w);
    uint2 hp, lp;
    hp.x = ((uint32_t)__bfloat16_as_ushort(h1) << 16) | __bfloat16_as_ushort(h0);
    hp.y = ((uint32_t)__bfloat16_as_ushort(h3) << 16) | __bfloat16_as_ushort(h2);
    lp.x = pack_bf16(v.x - __bfloat162float(h0), v.y - __bfloat162float(h1));
    lp.y = pack_bf16(v.z - __bfloat162float(h2), v.w - __bfloat162float(h3));
    *(uint2*)(g_xh + i * 4) = hp;
    *(uint2*)(g_xl + i * 4) = lp;
}

// ---------------- 2. HMMA split-bf16 GEMM ------------------------------------
// A register-staged, B via cp.async; 2 CTAs/SM. Tile 128x128, BK=32.
#define ROWB 80                 // padded smem row stride (bytes)
#define OAH 0
#define OAL 10240
#define OBH 20480
#define OBL 30720
#define STG 40960
#define SMEM_TOTAL (2*STG)

__device__ __forceinline__ void gemm_hmma(const __nv_bfloat16* __restrict__ Ah,
                                          const __nv_bfloat16* __restrict__ Al,
                                          const __nv_bfloat16* __restrict__ Bh,
                                          const __nv_bfloat16* __restrict__ Bl,
                                          float* __restrict__ C,
                                          const float* __restrict__ bias,
                                          int N, int K) {
    extern __shared__ char smem[];
    uint32_t sb = smem_to_u32(smem);
    int tid = threadIdx.x, lane = tid & 31, wid = tid >> 5;
    int m0 = blockIdx.y * 128, n0 = blockIdx.x * 128;
    int wm = (wid >> 2) * 64, wn = (wid & 3) * 32;

    uint32_t aOff = (uint32_t)((wm + (lane & 7) + ((lane >> 3) & 1) * 8) * ROWB
                               + ((lane >> 4) * 8) * 2);
    uint32_t bOff = (uint32_t)((wn + (lane & 7) + ((lane >> 4) & 1) * 8) * ROWB
                               + (((lane >> 3) & 1) * 8) * 2);

    float acc[4][4][4];
#pragma unroll
    for (int mt = 0; mt < 4; mt++)
#pragma unroll
        for (int nt = 0; nt < 4; nt++)
#pragma unroll
            for (int e = 0; e < 4; e++) acc[mt][nt][e] = 0.f;

    // copy mapping: thread t -> row = t>>1, 32B segment (t&1)
    int crow = tid >> 1;
    int cel = (tid & 1) * 16;                 // element offset (16 bf16 = 32B)
    uint32_t sOff = (uint32_t)(crow * ROWB + (tid & 1) * 32);
    const __nv_bfloat16* pAh = Ah + (size_t)(m0 + crow) * K + cel;
    const __nv_bfloat16* pAl = Al + (size_t)(m0 + crow) * K + cel;
    const __nv_bfloat16* pBh = Bh + (size_t)(n0 + crow) * K + cel;
    const __nv_bfloat16* pBl = Bl + (size_t)(n0 + crow) * K + cel;
    int nkc = K >> 5;

    uint4 rAh[2], rAl[2];
#define LOAD_A(kc) do {                                                 \
        int _ko = (kc) * 32;                                            \
        rAh[0] = *(const uint4*)(pAh + _ko); rAh[1] = *(const uint4*)(pAh + _ko + 8); \
        rAl[0] = *(const uint4*)(pAl + _ko); rAl[1] = *(const uint4*)(pAl + _ko + 8); \
    } while(0)
#define STORE_A(s) do {                                                 \
        char* _st = smem + (s) * STG;                                   \
        *(uint4*)(_st + OAH + sOff) = rAh[0]; *(uint4*)(_st + OAH + sOff + 16) = rAh[1]; \
        *(uint4*)(_st + OAL + sOff) = rAl[0]; *(uint4*)(_st + OAL + sOff + 16) = rAl[1]; \
    } while(0)
#define CP_B(kc, s) do {                                                \
        uint32_t _stb = sb + (s) * STG;                                 \
        int _ko = (kc) * 32;                                            \
        cp16(_stb + OBH + sOff,      pBh + _ko);                        \
        cp16(_stb + OBH + sOff + 16, pBh + _ko + 8);                    \
        cp16(_stb + OBL + sOff,      pBl + _ko);                        \
        cp16(_stb + OBL + sOff + 16, pBl + _ko + 8);                    \
    } while(0)

    LOAD_A(0);
    CP_B(0, 0);
    cp_commit();
    STORE_A(0);
    cp_wait0();
    __syncthreads();

    for (int kc = 0; kc < nkc; kc++) {
        bool more = (kc + 1 < nkc);
        int s = kc & 1;
        if (more) {
            LOAD_A(kc + 1);
            CP_B(kc + 1, s ^ 1);
        }
        cp_commit();

        uint32_t stb = sb + s * STG;
#pragma unroll
        for (int ks = 0; ks < 2; ks++) {
            uint32_t kb = ks * 32;
            uint32_t af[4][4], bhF[2][4], blF[2][4];
#pragma unroll
            for (int mt = 0; mt < 4; mt++)
                ldsm_x4(af[mt], stb + OAH + aOff + mt * (16 * ROWB) + kb);
#pragma unroll
            for (int np = 0; np < 2; np++) {
                ldsm_x4(bhF[np], stb + OBH + bOff + np * (16 * ROWB) + kb);
                ldsm_x4(blF[np], stb + OBL + bOff + np * (16 * ROWB) + kb);
            }
#pragma unroll
            for (int mt = 0; mt < 4; mt++)
#pragma unroll
                for (int nt = 0; nt < 4; nt++)
                    mma16816(acc[mt][nt], af[mt], &bhF[nt >> 1][(nt & 1) * 2]);
#pragma unroll
            for (int mt = 0; mt < 4; mt++)
#pragma unroll
                for (int nt = 0; nt < 4; nt++)
                    mma16816(acc[mt][nt], af[mt], &blF[nt >> 1][(nt & 1) * 2]);
#pragma unroll
            for (int mt = 0; mt < 4; mt++)
                ldsm_x4(af[mt], stb + OAL + aOff + mt * (16 * ROWB) + kb);
#pragma unroll
            for (int mt = 0; mt < 4; mt++)
#pragma unroll
                for (int nt = 0; nt < 4; nt++)
                    mma16816(acc[mt][nt], af[mt], &bhF[nt >> 1][(nt & 1) * 2]);
        }
        __syncthreads();
        if (more) {
            STORE_A(s ^ 1);
            cp_wait0();
        }
        __syncthreads();
    }
#undef LOAD_A
#undef STORE_A
#undef CP_B

    // epilogue
#pragma unroll
    for (int mt = 0; mt < 4; mt++) {
        int r0 = m0 + wm + mt * 16 + (lane >> 2);
#pragma unroll
        for (int nt = 0; nt < 4; nt++) {
            int col = n0 + wn + nt * 8 + (lane & 3) * 2;
            float b0 = 0.f, b1 = 0.f;
            if (bias) { b0 = bias[col]; b1 = bias[col + 1]; }
            float2 v0, v1;
            v0.x = acc[mt][nt][0] + b0; v0.y = acc[mt][nt][1] + b1;
            v1.x = acc[mt][nt][2] + b0; v1.y = acc[mt][nt][3] + b1;
            *(float2*)(C + (size_t)r0 * N + col) = v0;
            *(float2*)(C + (size_t)(r0 + 8) * N + col) = v1;
        }
    }
}

__global__ __launch_bounds__(256, 2) void gemm1_tc() {
    gemm_hmma(g_xh, g_xl, g_Bt1h, g_Bt1l, g_proj, nullptr, NP1, NF);
}
__global__ __launch_bounds__(256, 2) void gemm2_tc(const float* __restrict__ bout,
                                                   float* __restrict__ y) {
    gemm_hmma(g_o2h, g_o2l, g_Bt2h, g_Bt2l, y, bout, NF, HID);
}

// ------- 3. activations + l2norm + fused action proj (transposed weights) ---
__global__ __launch_bounds__(256) void act_kernel(const float* __restrict__ mask,
                                                  const float* __restrict__ action) {
    __shared__ float s_act[ACTF];
    int bs = blockIdx.x;                 // block = one (b,s) row; 8 warps = 8 heads
    int tid = threadIdx.x;
    int h = tid >> 5, lane = tid & 31;
    if (tid < ACTF) s_act[tid] = action[bs * ACTF + tid];
    __syncthreads();

    int w = bs * NH + h;
    int pb = bs * NP1;

    // action projection: lane owns col c = h*32+lane, reads 16 contiguous weights
    int c = h * 32 + lane;
    float4 a0 = *(const float4*)&s_act[0];
    float4 a1 = *(const float4*)&s_act[4];
    float4 a2 = *(const float4*)&s_act[8];
    float4 a3 = *(const float4*)&s_act[12];
    const float4* wk = (const float4*)&g_WkuT[c * ACTF];
    const float4* wv = (const float4*)&g_WvuT[c * ACTF];
    float kur, vur;
    {
        float4 w0 = wk[0], w1 = wk[1], w2 = wk[2], w3 = wk[3];
        kur = a0.x*w0.x + a0.y*w0.y + a0.z*w0.z + a0.w*w0.w
            + a1.x*w1.x + a1.y*w1.y + a1.z*w1.z + a1.w*w1.w
            + a2.x*w2.x + a2.y*w2.y + a2.z*w2.z + a2.w*w2.w
            + a3.x*w3.x + a3.y*w3.y + a3.z*w3.z + a3.w*w3.w;
        float4 v0 = wv[0], v1 = wv[1], v2 = wv[2], v3 = wv[3];
        vur = a0.x*v0.x + a0.y*v0.y + a0.z*v0.z + a0.w*v0.w
            + a1.x*v1.x + a1.y*v1.y + a1.z*v1.z + a1.w*v1.w
            + a2.x*v2.x + a2.y*v2.y + a2.z*v2.z + a2.w*v2.w
            + a3.x*v3.x + a3.y*v3.y + a3.z*v3.z + a3.w*v3.w;
    }
    // gamma: warp reduce over lanes<16
    float gp = (lane < ACTF) ? s_act[lane] * g_WgT[h * ACTF + lane] : 0.f;
#pragma unroll
    for (int o = 16; o > 0; o >>= 1) gp += __shfl_xor_sync(0xffffffffu, gp, o);
    float gr = gp;

    float qr  = g_proj[pb + h*32 + lane];
    float kr  = g_proj[pb + 256 + h*32 + lane];
    float vr  = g_proj[pb + 512 + h*32 + lane];

    float q  = qr * sigm(qr);
    float k  = kr * sigm(kr);
    float ku = kur * sigm(kur);

    float sq = q*q, sk = k*k, sku = ku*ku;
#pragma unroll
    for (int o = 16; o > 0; o >>= 1) {
        sq  += __shfl_xor_sync(0xffffffffu, sq,  o);
        sk  += __shfl_xor_sync(0xffffffffu, sk,  o);
        sku += __shfl_xor_sync(0xffffffffu, sku, o);
    }
    q  *= rsqrtf(sq  + EPSF);
    k  *= rsqrtf(sk  + EPSF);
    ku *= rsqrtf(sku + EPSF);

    float dk = ku * k;
#pragma unroll
    for (int o = 16; o > 0; o >>= 1) dk += __shfl_xor_sync(0xffffffffu, dk, o);

    int base = w * 32;
    g_qn[base + lane]  = q;
    g_kn[base + lane]  = k;
    g_kun[base + lane] = ku;
    g_vs[base + lane]  = vr;
    g_vu[base + lane]  = vur;
    if (lane == 0) {
        float br = g_proj[pb + 768 + h];
        float ar = g_proj[pb + 776 + h];
        float m  = mask[bs];
        g_sc[w*4 + 0] = sigm(br);                 // beta
        g_sc[w*4 + 1] = sigm(ar) * (1.f - m);     // Aeff
        g_sc[w*4 + 2] = sigm(gr);                 // Bg
        g_sc[w*4 + 3] = dk;                       // ku . k
    }
}

// ---------------- 5. phase 1: chunked scan, smem-broadcast operands ---------
__global__ __launch_bounds__(128) void phase1() {
    __shared__ float sk[4][32], sq[4][32], sku[4][32];
    int wq = threadIdx.x >> 5;
    int wg = blockIdx.x * 4 + wq;                   // 0..1023
    int lane = threadIdx.x & 31;
    int chain = wg >> 5;        // b*8+h
    int c = wg & 31;
    int b = chain >> 3, h = chain & 7;

    float cum[32], hl[32];
#pragma unroll
    for (int j = 0; j < 32; j++) { cum[j] = (j == lane) ? 1.f : 0.f; hl[j] = 0.f; }

    int t0 = c * CHUNK;
    int base = ((b * NS + t0) * NH + h) * 32;
    float kreg  = g_kn[base + lane];
    float qreg  = g_qn[base + lane];
    float kureg = g_kun[base + lane];
    float vs    = g_vs[base + lane];
    float vu    = g_vu[base + lane];
    float4 scv  = *(const float4*)&g_sc[((b * NS + t0) * NH + h) * 4];

    for (int t = t0; t < t0 + CHUNK; t++) {
        __syncwarp();
        sk[wq][lane]  = kreg;
        sq[wq][lane]  = qreg;
        sku[wq][lane] = kureg;
        __syncwarp();

        // prefetch next timestep
        float kN = 0.f, qN = 0.f, kuN = 0.f, vsN = 0.f, vuN = 0.f;
        float4 scN = scv;
        int base2 = base;
        if (t + 1 < t0 + CHUNK) {
            int w2 = (b * NS + t + 1) * NH + h;
            base2 = w2 * 32;
            kN  = g_kn[base2 + lane];
            qN  = g_qn[base2 + lane];
            kuN = g_kun[base2 + lane];
            vsN = g_vs[base2 + lane];
            vuN = g_vu[base2 + lane];
            scN = *(const float4*)&g_sc[w2 * 4];
        }

        float beta = scv.x, Ae = scv.y, Bg = scv.z, kuk = scv.w;
        float ck = 0.f, hk = 0.f;
#pragma unroll
        for (int j4 = 0; j4 < 8; j4++) {
            float4 k4 = *(const float4*)&sk[wq][j4 * 4];
            ck += cum[j4*4+0]*k4.x + cum[j4*4+1]*k4.y + cum[j4*4+2]*k4.z + cum[j4*4+3]*k4.w;
            hk += hl[j4*4+0]*k4.x  + hl[j4*4+1]*k4.y  + hl[j4*4+2]*k4.z  + hl[j4*4+3]*k4.w;
        }
        float e  = Ae * beta * ck;
        float cc = beta * vs - Ae * beta * hk - Bg * beta * kuk * vu;
        float dd = Bg * vu;

        float u = 0.f, wv = 0.f;
#pragma unroll
        for (int j4 = 0; j4 < 8; j4++) {
            float4 k4  = *(const float4*)&sk[wq][j4 * 4];
            float4 ku4 = *(const float4*)&sku[wq][j4 * 4];
            float4 q4  = *(const float4*)&sq[wq][j4 * 4];
            int j = j4 * 4;
            cum[j+0] = Ae * cum[j+0] - e * k4.x;
            cum[j+1] = Ae * cum[j+1] - e * k4.y;
            cum[j+2] = Ae * cum[j+2] - e * k4.z;
            cum[j+3] = Ae * cum[j+3] - e * k4.w;
            hl[j+0] = Ae * hl[j+0] + cc * k4.x + dd * ku4.x;
            hl[j+1] = Ae * hl[j+1] + cc * k4.y + dd * ku4.y;
            hl[j+2] = Ae * hl[j+2] + cc * k4.z + dd * ku4.z;
            hl[j+3] = Ae * hl[j+3] + cc * k4.w + dd * ku4.w;
            u  += cum[j+0]*q4.x + cum[j+1]*q4.y + cum[j+2]*q4.z + cum[j+3]*q4.w;
            wv += hl[j+0]*q4.x  + hl[j+1]*q4.y  + hl[j+2]*q4.z  + hl[j+3]*q4.w;
        }
        g_u[base + lane] = u;
        g_w[base + lane] = wv;

        kreg = kN; qreg = qN; kureg = kuN; vs = vsN; vu = vuN; scv = scN;
        base = base2;
    }
    int mb = (chain * NC + c) * 1024 + lane * 32;
#pragma unroll
    for (int j = 0; j < 32; j += 4) {
        *(float4*)&g_cum[mb + j] = make_float4(cum[j], cum[j+1], cum[j+2], cum[j+3]);
        *(float4*)&g_loc[mb + j] = make_float4(hl[j],  hl[j+1],  hl[j+2],  hl[j+3]);
    }
}

// ---------------- 6. phase 2: fold chunks (smem-staged, prefetched) ---------
__global__ __launch_bounds__(1024) void phase2(const float* __restrict__ carry,
                                               float* __restrict__ outCarry) {
    __shared__ float cumS[2][1024];
    int chain = blockIdx.x;
    int tid = threadIdx.x;
    int j = tid & 31;
    float hreg = carry[chain * 1024 + tid];

    int mb0 = (chain * NC) * 1024;
    float cumNext = g_cum[mb0 + tid];
    float locNext = g_loc[mb0 + tid];

    for (int c = 0; c < NC; c++) {
        int s = c & 1;
        cumS[s][tid] = cumNext;
        float locCur = locNext;
        __syncthreads();
        if (c + 1 < NC) {
            int mb1 = (chain * NC + c + 1) * 1024;
            cumNext = g_cum[mb1 + tid];
            locNext = g_loc[mb1 + tid];
        }
        g_hinit[(chain * NC + c) * 1024 + tid] = hreg;   // state at chunk start
        float nv = locCur;
#pragma unroll
        for (int m = 0; m < 32; m++)
            nv += __shfl_sync(0xffffffffu, hreg, m) * cumS[s][m * 32 + j];
        hreg = nv;
    }
    outCarry[chain * 1024 + tid] = hreg;  // new_carry
}

// --------- 7. fused phase3 + rms + split: block per (b, chunk) ---------------
__global__ __launch_bounds__(512) void phase3_rms(const float* __restrict__ scale) {
    __shared__ float hin[NH][32 * 33];
    __shared__ float sscale[HID];
    __shared__ float partial[2][NH];
    int blk = blockIdx.x;            // b*NC + c
    int b = blk >> 5, c = blk & 31;
    int tid = threadIdx.x;
    int wid = tid >> 5, lane = tid & 31;
    int h = wid & 7, half = wid >> 3;

    for (int idx = tid; idx < NH * 1024; idx += 512) {
        int hh = idx >> 10, e = idx & 1023;
        int i = e >> 5, jj = e & 31;
        hin[hh][i * 33 + jj] = g_hinit[(((b * NH + hh) * NC) + c) * 1024 + e];
    }
    if (tid < HID) sscale[tid] = scale[tid];
    __syncthreads();

    for (int it = 0; it < 32; it++) {
        int t = c * CHUNK + half * 32 + it;
        int bsrow = b * NS + t;
        int base = (bsrow * NH + h) * 32;
        float ul  = g_u[base + lane];
        float acc = g_w[base + lane];
#pragma unroll
        for (int j = 0; j < 32; j++)
            acc += hin[h][lane * 33 + j] * __shfl_sync(0xffffffffu, ul, j);

        // rms over the 256 values of this (b,t): 8 warps participate per half
        float ss = acc * acc;
#pragma unroll
        for (int o = 16; o > 0; o >>= 1) ss += __shfl_xor_sync(0xffffffffu, ss, o);
        if (lane == 0) partial[half][h] = ss;
        __syncthreads();
        float tot = partial[half][0] + partial[half][1] + partial[half][2] + partial[half][3]
                  + partial[half][4] + partial[half][5] + partial[half][6] + partial[half][7];
        float inv = rsqrtf(tot * (1.f / 256.f) + EPSF);
        float o = acc * inv * sscale[h * 32 + lane];
        __nv_bfloat16 hv = __float2bfloat16(o);
        int oidx = bsrow * HID + h * 32 + lane;
        g_o2h[oidx] = hv;
        g_o2l[oidx] = __float2bfloat16(o - __bfloat162float(hv));
        __syncthreads();
    }
}

// ---------------- launcher ---------------------------------------------------
extern "C" void kernel_launch(void* const* d_in, const int* in_sizes, int n_in,
                              void* d_out, int out_size) {
    const float* x      = (const float*)d_in[0];
    const float* action = (const float*)d_in[1];
    const float* mask   = (const float*)d_in[2];
    const float* carry  = (const float*)d_in[3];
    const float* Wq     = (const float*)d_in[4];
    const float* Wk     = (const float*)d_in[5];
    const float* Wv     = (const float*)d_in[6];
    const float* Wbeta  = (const float*)d_in[7];
    const float* Walpha = (const float*)d_in[8];
    const float* Wku    = (const float*)d_in[9];
    const float* Wvu    = (const float*)d_in[10];
    const float* Wgamma = (const float*)d_in[11];
    const float* rmssc  = (const float*)d_in[12];
    const float* Wout   = (const float*)d_in[13];
    const float* bout   = (const float*)d_in[14];

    float* outCarry = (float*)d_out;                       // (B,H,D,D) = 32768
    float* y        = (float*)d_out + NB * NH * ND * ND;   // (B,S,F)

    cudaFuncSetAttribute(gemm1_tc, cudaFuncAttributeMaxDynamicSharedMemorySize, SMEM_TOTAL);
    cudaFuncSetAttribute(gemm2_tc, cudaFuncAttributeMaxDynamicSharedMemorySize, SMEM_TOTAL);

    int nprep = N1ELEM + N2ELEM + N3ELEM + NH * ACTF;
    prep_weights<<<(nprep + 255) / 256, 256>>>(Wq, Wk, Wv, Wbeta, Walpha, Wout,
                                               Wku, Wvu, Wgamma);
    split_x<<<(ROWS * NF / 4) / 256, 256>>>(x);

    dim3 g1(NP1 / 128, ROWS / 128);       // (7, 64)
    gemm1_tc<<<g1, 256, SMEM_TOTAL>>>();

    act_kernel<<<ROWS, 256>>>(mask, action);

    phase1<<<256, 128>>>();
    phase2<<<32, 1024>>>(carry, outCarry);
    phase3_rms<<<NB * NC, 512>>>(rmssc);

    dim3 g2(NF / 128, ROWS / 128);        // (4, 64)
    gemm2_tc<<<g2, 256, SMEM_TOTAL>>>(bout, y);
}

// round 7
// speedup vs baseline: 1.1176x; 1.0064x over previous
#include <cuda_runtime.h>
#include <cuda_bf16.h>
#include <cstdint>

// Problem constants
#define NB 4
#define NS 2048
#define NF 512
#define NH 8
#define ND 32
#define HID 256
#define ACTF 16
#define ROWS (NB*NS)          // 8192
#define NP1 896               // padded x-proj output width
#define NC 32                 // chunks per sequence
#define CHUNK 64              // NS / NC
#define EPSF 1e-6f

// ---------------- scratch (static device globals; no allocations) ----------
__device__ __nv_bfloat16 g_Bt1h[NP1*NF];   // [896,512] W1^T hi
__device__ __nv_bfloat16 g_Bt1l[NP1*NF];
__device__ __nv_bfloat16 g_Bt2h[NF*HID];   // [512,256] Wout^T hi
__device__ __nv_bfloat16 g_Bt2l[NF*HID];
__device__ __nv_bfloat16 g_xh[ROWS*NF];    // split x
__device__ __nv_bfloat16 g_xl[ROWS*NF];
__device__ __nv_bfloat16 g_o2h[ROWS*HID];  // split rms output (GEMM2 A)
__device__ __nv_bfloat16 g_o2l[ROWS*HID];
__device__ float g_WkuT[HID*ACTF];         // transposed action weights
__device__ float g_WvuT[HID*ACTF];
__device__ float g_WgT[NH*ACTF];
__device__ float g_proj[ROWS*NP1];
__device__ float g_qn[ROWS*HID];
__device__ float g_kn[ROWS*HID];
__device__ float g_kun[ROWS*HID];
__device__ float g_vs[ROWS*HID];
__device__ float g_vu[ROWS*HID];
__device__ float g_sc[ROWS*NH*4];        // beta, Aeff, Bg, ku.k
__device__ float g_u[ROWS*HID];
__device__ float g_w[ROWS*HID];
__device__ float g_cum[32*NC*ND*ND];
__device__ float g_loc[32*NC*ND*ND];
__device__ float g_hinit[32*NC*ND*ND];

__device__ __forceinline__ float sigm(float z) { return 1.f / (1.f + __expf(-z)); }

__device__ __forceinline__ uint32_t smem_to_u32(const void* smem_ptr) {
    uint32_t addr;
    asm("{ .reg .u64 tmp; cvta.to.shared.u64 tmp, %1; cvt.u32.u64 %0, tmp; }"
        : "=r"(addr) : "l"(smem_ptr));
    return addr;
}
__device__ __forceinline__ void ldsm_x4(uint32_t* r, uint32_t addr) {
    asm volatile("ldmatrix.sync.aligned.m8n8.x4.shared.b16 {%0,%1,%2,%3}, [%4];"
        : "=r"(r[0]), "=r"(r[1]), "=r"(r[2]), "=r"(r[3]) : "r"(addr));
}
__device__ __forceinline__ void mma16816(float* d, const uint32_t* a, const uint32_t* b) {
    asm volatile(
        "mma.sync.aligned.m16n8k16.row.col.f32.bf16.bf16.f32 "
        "{%0,%1,%2,%3}, {%4,%5,%6,%7}, {%8,%9}, {%0,%1,%2,%3};"
        : "+f"(d[0]), "+f"(d[1]), "+f"(d[2]), "+f"(d[3])
        : "r"(a[0]), "r"(a[1]), "r"(a[2]), "r"(a[3]), "r"(b[0]), "r"(b[1]));
}
__device__ __forceinline__ void cp16(uint32_t saddr, const void* gaddr) {
    asm volatile("cp.async.cg.shared.global [%0], [%1], 16;" :: "r"(saddr), "l"(gaddr));
}
__device__ __forceinline__ void cp_commit() {
    asm volatile("cp.async.commit_group;" ::: "memory");
}
__device__ __forceinline__ void cp_wait0() {
    asm volatile("cp.async.wait_group 0;" ::: "memory");
}
__device__ __forceinline__ uint32_t pack_bf16(float x, float y) {
    __nv_bfloat16 hx = __float2bfloat16(x), hy = __float2bfloat16(y);
    return ((uint32_t)__bfloat16_as_ushort(hy) << 16) | __bfloat16_as_ushort(hx);
}

// ---------------- 1. weight prep ---------------------------------------------
#define N1ELEM (NP1*NF)
#define N2ELEM (NF*HID)
#define N3ELEM (HID*ACTF)
__global__ void prep_weights(const float* __restrict__ Wq, const float* __restrict__ Wk,
                             const float* __restrict__ Wv, const float* __restrict__ Wb,
                             const float* __restrict__ Wa, const float* __restrict__ Wout,
                             const float* __restrict__ Wku, const float* __restrict__ Wvu,
                             const float* __restrict__ Wg) {
    int i = blockIdx.x * blockDim.x + threadIdx.x;
    if (i < N1ELEM) {
        int n = i >> 9, k = i & 511;          // Bt1[n,k] = W1[k,n]
        float v = 0.f;
        if (n < 256)       v = Wq[k*256 + n];
        else if (n < 512)  v = Wk[k*256 + n - 256];
        else if (n < 768)  v = Wv[k*256 + n - 512];
        else if (n < 776)  v = Wb[k*8 + n - 768];
        else if (n < 784)  v = Wa[k*8 + n - 776];
        __nv_bfloat16 h = __float2bfloat16(v);
        g_Bt1h[i] = h;
        g_Bt1l[i] = __float2bfloat16(v - __bfloat162float(h));
    } else if (i < N1ELEM + N2ELEM) {
        int j = i - N1ELEM;
        int n = j >> 8, k = j & 255;          // Bt2[n,k] = Wout[k,n]
        float v = Wout[k*512 + n];
        __nv_bfloat16 h = __float2bfloat16(v);
        g_Bt2h[j] = h;
        g_Bt2l[j] = __float2bfloat16(v - __bfloat162float(h));
    } else if (i < N1ELEM + N2ELEM + N3ELEM) {
        int j = i - N1ELEM - N2ELEM;
        int c = j >> 4, k = j & 15;
        g_WkuT[j] = Wku[k*HID + c];
        g_WvuT[j] = Wvu[k*HID + c];
    } else if (i < N1ELEM + N2ELEM + N3ELEM + NH*ACTF) {
        int j = i - N1ELEM - N2ELEM - N3ELEM;
        int h = j >> 4, k = j & 15;
        g_WgT[j] = Wg[k*NH + h];
    }
}

// ---------------- 1b. split x into hi/lo bf16 -------------------------------
__global__ __launch_bounds__(256) void split_x(const float* __restrict__ x) {
    int i = blockIdx.x * blockDim.x + threadIdx.x;   // float4 index
    float4 v = *(const float4*)(x + i * 4);
    __nv_bfloat16 h0 = __float2bfloat16(v.x), h1 = __float2bfloat16(v.y);
    __nv_bfloat16 h2 = __float2bfloat16(v.z), h3 = __float2bfloat16(v.w);
    uint2 hp, lp;
    hp.x = ((uint32_t)__bfloat16_as_ushort(h1) << 16) | __bfloat16_as_ushort(h0);
    hp.y = ((uint32_t)__bfloat16_as_ushort(h3) << 16) | __bfloat16_as_ushort(h2);
    lp.x = pack_bf16(v.x - __bfloat162float(h0), v.y - __bfloat162float(h1));
    lp.y = pack_bf16(v.z - __bfloat162float(h2), v.w - __bfloat162float(h3));
    *(uint2*)(g_xh + i * 4) = hp;
    *(uint2*)(g_xl + i * 4) = lp;
}

// ---------------- 2. HMMA split-bf16 GEMM ------------------------------------
// A register-staged, B via cp.async; 2 CTAs/SM. Tile 128x128, BK=32.
#define ROWB 80                 // padded smem row stride (bytes)
#define OAH 0
#define OAL 10240
#define OBH 20480
#define OBL 30720
#define STG 40960
#define SMEM_TOTAL (2*STG)

__device__ __forceinline__ void gemm_hmma(const __nv_bfloat16* __restrict__ Ah,
                                          const __nv_bfloat16* __restrict__ Al,
                                          const __nv_bfloat16* __restrict__ Bh,
                                          const __nv_bfloat16* __restrict__ Bl,
                                          float* __restrict__ C,
                                          const float* __restrict__ bias,
                                          int N, int K) {
    extern __shared__ char smem[];
    uint32_t sb = smem_to_u32(smem);
    int tid = threadIdx.x, lane = tid & 31, wid = tid >> 5;
    int m0 = blockIdx.y * 128, n0 = blockIdx.x * 128;
    int wm = (wid >> 2) * 64, wn = (wid & 3) * 32;

    uint32_t aOff = (uint32_t)((wm + (lane & 7) + ((lane >> 3) & 1) * 8) * ROWB
                               + ((lane >> 4) * 8) * 2);
    uint32_t bOff = (uint32_t)((wn + (lane & 7) + ((lane >> 4) & 1) * 8) * ROWB
                               + (((lane >> 3) & 1) * 8) * 2);

    float acc[4][4][4];
#pragma unroll
    for (int mt = 0; mt < 4; mt++)
#pragma unroll
        for (int nt = 0; nt < 4; nt++)
#pragma unroll
            for (int e = 0; e < 4; e++) acc[mt][nt][e] = 0.f;

    int crow = tid >> 1;
    int cel = (tid & 1) * 16;
    uint32_t sOff = (uint32_t)(crow * ROWB + (tid & 1) * 32);
    const __nv_bfloat16* pAh = Ah + (size_t)(m0 + crow) * K + cel;
    const __nv_bfloat16* pAl = Al + (size_t)(m0 + crow) * K + cel;
    const __nv_bfloat16* pBh = Bh + (size_t)(n0 + crow) * K + cel;
    const __nv_bfloat16* pBl = Bl + (size_t)(n0 + crow) * K + cel;
    int nkc = K >> 5;

    uint4 rAh[2], rAl[2];
#define LOAD_A(kc) do {                                                 \
        int _ko = (kc) * 32;                                            \
        rAh[0] = *(const uint4*)(pAh + _ko); rAh[1] = *(const uint4*)(pAh + _ko + 8); \
        rAl[0] = *(const uint4*)(pAl + _ko); rAl[1] = *(const uint4*)(pAl + _ko + 8); \
    } while(0)
#define STORE_A(s) do {                                                 \
        char* _st = smem + (s) * STG;                                   \
        *(uint4*)(_st + OAH + sOff) = rAh[0]; *(uint4*)(_st + OAH + sOff + 16) = rAh[1]; \
        *(uint4*)(_st + OAL + sOff) = rAl[0]; *(uint4*)(_st + OAL + sOff + 16) = rAl[1]; \
    } while(0)
#define CP_B(kc, s) do {                                                \
        uint32_t _stb = sb + (s) * STG;                                 \
        int _ko = (kc) * 32;                                            \
        cp16(_stb + OBH + sOff,      pBh + _ko);                        \
        cp16(_stb + OBH + sOff + 16, pBh + _ko + 8);                    \
        cp16(_stb + OBL + sOff,      pBl + _ko);                        \
        cp16(_stb + OBL + sOff + 16, pBl + _ko + 8);                    \
    } while(0)

    LOAD_A(0);
    CP_B(0, 0);
    cp_commit();
    STORE_A(0);
    cp_wait0();
    __syncthreads();

    for (int kc = 0; kc < nkc; kc++) {
        bool more = (kc + 1 < nkc);
        int s = kc & 1;
        if (more) {
            LOAD_A(kc + 1);
            CP_B(kc + 1, s ^ 1);
        }
        cp_commit();

        uint32_t stb = sb + s * STG;
#pragma unroll
        for (int ks = 0; ks < 2; ks++) {
            uint32_t kb = ks * 32;
            uint32_t af[4][4], bhF[2][4], blF[2][4];
#pragma unroll
            for (int mt = 0; mt < 4; mt++)
                ldsm_x4(af[mt], stb + OAH + aOff + mt * (16 * ROWB) + kb);
#pragma unroll
            for (int np = 0; np < 2; np++) {
                ldsm_x4(bhF[np], stb + OBH + bOff + np * (16 * ROWB) + kb);
                ldsm_x4(blF[np], stb + OBL + bOff + np * (16 * ROWB) + kb);
            }
#pragma unroll
            for (int mt = 0; mt < 4; mt++)
#pragma unroll
                for (int nt = 0; nt < 4; nt++)
                    mma16816(acc[mt][nt], af[mt], &bhF[nt >> 1][(nt & 1) * 2]);
#pragma unroll
            for (int mt = 0; mt < 4; mt++)
#pragma unroll
                for (int nt = 0; nt < 4; nt++)
                    mma16816(acc[mt][nt], af[mt], &blF[nt >> 1][(nt & 1) * 2]);
#pragma unroll
            for (int mt = 0; mt < 4; mt++)
                ldsm_x4(af[mt], stb + OAL + aOff + mt * (16 * ROWB) + kb);
#pragma unroll
            for (int mt = 0; mt < 4; mt++)
#pragma unroll
                for (int nt = 0; nt < 4; nt++)
                    mma16816(acc[mt][nt], af[mt], &bhF[nt >> 1][(nt & 1) * 2]);
        }
        __syncthreads();
        if (more) {
            STORE_A(s ^ 1);
            cp_wait0();
        }
        __syncthreads();
    }
#undef LOAD_A
#undef STORE_A
#undef CP_B

    // epilogue
#pragma unroll
    for (int mt = 0; mt < 4; mt++) {
        int r0 = m0 + wm + mt * 16 + (lane >> 2);
#pragma unroll
        for (int nt = 0; nt < 4; nt++) {
            int col = n0 + wn + nt * 8 + (lane & 3) * 2;
            float b0 = 0.f, b1 = 0.f;
            if (bias) { b0 = bias[col]; b1 = bias[col + 1]; }
            float2 v0, v1;
            v0.x = acc[mt][nt][0] + b0; v0.y = acc[mt][nt][1] + b1;
            v1.x = acc[mt][nt][2] + b0; v1.y = acc[mt][nt][3] + b1;
            *(float2*)(C + (size_t)r0 * N + col) = v0;
            *(float2*)(C + (size_t)(r0 + 8) * N + col) = v1;
        }
    }
}

__global__ __launch_bounds__(256, 2) void gemm1_tc() {
    gemm_hmma(g_xh, g_xl, g_Bt1h, g_Bt1l, g_proj, nullptr, NP1, NF);
}
__global__ __launch_bounds__(256, 2) void gemm2_tc(const float* __restrict__ bout,
                                                   float* __restrict__ y) {
    gemm_hmma(g_o2h, g_o2l, g_Bt2h, g_Bt2l, y, bout, NF, HID);
}

// ------- 3. activations + l2norm + fused action proj (barrier-free) ---------
__global__ __launch_bounds__(256) void act_kernel(const float* __restrict__ mask,
                                                  const float* __restrict__ action) {
    int w = (blockIdx.x * blockDim.x + threadIdx.x) >> 5;   // (b*S+s)*H + h
    int lane = threadIdx.x & 31;
    if (w >= ROWS * NH) return;
    int bs = w >> 3, h = w & 7;
    int pb = bs * NP1;

    // action row: 64B broadcast loads (all lanes same address)
    const float4* ar4 = (const float4*)(action + bs * ACTF);
    float4 a0 = ar4[0], a1 = ar4[1], a2 = ar4[2], a3 = ar4[3];

    // transposed weights: lane owns col c = h*32+lane, 16 contiguous floats
    int c = h * 32 + lane;
    const float4* wk = (const float4*)&g_WkuT[c * ACTF];
    const float4* wv = (const float4*)&g_WvuT[c * ACTF];
    float kur, vur;
    {
        float4 w0 = wk[0], w1 = wk[1], w2 = wk[2], w3 = wk[3];
        kur = a0.x*w0.x + a0.y*w0.y + a0.z*w0.z + a0.w*w0.w
            + a1.x*w1.x + a1.y*w1.y + a1.z*w1.z + a1.w*w1.w
            + a2.x*w2.x + a2.y*w2.y + a2.z*w2.z + a2.w*w2.w
            + a3.x*w3.x + a3.y*w3.y + a3.z*w3.z + a3.w*w3.w;
        float4 v0 = wv[0], v1 = wv[1], v2 = wv[2], v3 = wv[3];
        vur = a0.x*v0.x + a0.y*v0.y + a0.z*v0.z + a0.w*v0.w
            + a1.x*v1.x + a1.y*v1.y + a1.z*v1.z + a1.w*v1.w
            + a2.x*v2.x + a2.y*v2.y + a2.z*v2.z + a2.w*v2.w
            + a3.x*v3.x + a3.y*v3.y + a3.z*v3.z + a3.w*v3.w;
    }
    // gamma (per-head scalar): 16-float dot, broadcast loads
    float gr;
    {
        const float4* wg = (const float4*)&g_WgT[h * ACTF];
        float4 g0 = wg[0], g1 = wg[1], g2 = wg[2], g3 = wg[3];
        gr = a0.x*g0.x + a0.y*g0.y + a0.z*g0.z + a0.w*g0.w
           + a1.x*g1.x + a1.y*g1.y + a1.z*g1.z + a1.w*g1.w
           + a2.x*g2.x + a2.y*g2.y + a2.z*g2.z + a2.w*g2.w
           + a3.x*g3.x + a3.y*g3.y + a3.z*g3.z + a3.w*g3.w;
    }

    float qr  = g_proj[pb + h*32 + lane];
    float kr  = g_proj[pb + 256 + h*32 + lane];
    float vr  = g_proj[pb + 512 + h*32 + lane];

    float q  = qr * sigm(qr);
    float k  = kr * sigm(kr);
    float ku = kur * sigm(kur);

    float sq = q*q, sk = k*k, sku = ku*ku;
#pragma unroll
    for (int o = 16; o > 0; o >>= 1) {
        sq  += __shfl_xor_sync(0xffffffffu, sq,  o);
        sk  += __shfl_xor_sync(0xffffffffu, sk,  o);
        sku += __shfl_xor_sync(0xffffffffu, sku, o);
    }
    q  *= rsqrtf(sq  + EPSF);
    k  *= rsqrtf(sk  + EPSF);
    ku *= rsqrtf(sku + EPSF);

    float dk = ku * k;
#pragma unroll
    for (int o = 16; o > 0; o >>= 1) dk += __shfl_xor_sync(0xffffffffu, dk, o);

    int base = w * 32;
    g_qn[base + lane]  = q;
    g_kn[base + lane]  = k;
    g_kun[base + lane] = ku;
    g_vs[base + lane]  = vr;
    g_vu[base + lane]  = vur;
    if (lane == 0) {
        float br = g_proj[pb + 768 + h];
        float ar = g_proj[pb + 776 + h];
        float m  = mask[bs];
        g_sc[w*4 + 0] = sigm(br);                 // beta
        g_sc[w*4 + 1] = sigm(ar) * (1.f - m);     // Aeff
        g_sc[w*4 + 2] = sigm(gr);                 // Bg
        g_sc[w*4 + 3] = dk;                       // ku . k
    }
}

// ---------------- 5. phase 1: chunked scan, smem-broadcast operands ---------
__global__ __launch_bounds__(128) void phase1() {
    __shared__ float sk[4][32], sq[4][32], sku[4][32];
    int wq = threadIdx.x >> 5;
    int wg = blockIdx.x * 4 + wq;                   // 0..1023
    int lane = threadIdx.x & 31;
    int chain = wg >> 5;        // b*8+h
    int c = wg & 31;
    int b = chain >> 3, h = chain & 7;

    float cum[32], hl[32];
#pragma unroll
    for (int j = 0; j < 32; j++) { cum[j] = (j == lane) ? 1.f : 0.f; hl[j] = 0.f; }

    int t0 = c * CHUNK;
    int base = ((b * NS + t0) * NH + h) * 32;
    float kreg  = g_kn[base + lane];
    float qreg  = g_qn[base + lane];
    float kureg = g_kun[base + lane];
    float vs    = g_vs[base + lane];
    float vu    = g_vu[base + lane];
    float4 scv  = *(const float4*)&g_sc[((b * NS + t0) * NH + h) * 4];

    for (int t = t0; t < t0 + CHUNK; t++) {
        __syncwarp();
        sk[wq][lane]  = kreg;
        sq[wq][lane]  = qreg;
        sku[wq][lane] = kureg;
        __syncwarp();

        // prefetch next timestep
        float kN = 0.f, qN = 0.f, kuN = 0.f, vsN = 0.f, vuN = 0.f;
        float4 scN = scv;
        int base2 = base;
        if (t + 1 < t0 + CHUNK) {
            int w2 = (b * NS + t + 1) * NH + h;
            base2 = w2 * 32;
            kN  = g_kn[base2 + lane];
            qN  = g_qn[base2 + lane];
            kuN = g_kun[base2 + lane];
            vsN = g_vs[base2 + lane];
            vuN = g_vu[base2 + lane];
            scN = *(const float4*)&g_sc[w2 * 4];
        }

        float beta = scv.x, Ae = scv.y, Bg = scv.z, kuk = scv.w;
        float ck = 0.f, hk = 0.f;
#pragma unroll
        for (int j4 = 0; j4 < 8; j4++) {
            float4 k4 = *(const float4*)&sk[wq][j4 * 4];
            ck += cum[j4*4+0]*k4.x + cum[j4*4+1]*k4.y + cum[j4*4+2]*k4.z + cum[j4*4+3]*k4.w;
            hk += hl[j4*4+0]*k4.x  + hl[j4*4+1]*k4.y  + hl[j4*4+2]*k4.z  + hl[j4*4+3]*k4.w;
        }
        float e  = Ae * beta * ck;
        float cc = beta * vs - Ae * beta * hk - Bg * beta * kuk * vu;
        float dd = Bg * vu;

        float u = 0.f, wv = 0.f;
#pragma unroll
        for (int j4 = 0; j4 < 8; j4++) {
            float4 k4  = *(const float4*)&sk[wq][j4 * 4];
            float4 ku4 = *(const float4*)&sku[wq][j4 * 4];
            float4 q4  = *(const float4*)&sq[wq][j4 * 4];
            int j = j4 * 4;
            cum[j+0] = Ae * cum[j+0] - e * k4.x;
            cum[j+1] = Ae * cum[j+1] - e * k4.y;
            cum[j+2] = Ae * cum[j+2] - e * k4.z;
            cum[j+3] = Ae * cum[j+3] - e * k4.w;
            hl[j+0] = Ae * hl[j+0] + cc * k4.x + dd * ku4.x;
            hl[j+1] = Ae * hl[j+1] + cc * k4.y + dd * ku4.y;
            hl[j+2] = Ae * hl[j+2] + cc * k4.z + dd * ku4.z;
            hl[j+3] = Ae * hl[j+3] + cc * k4.w + dd * ku4.w;
            u  += cum[j+0]*q4.x + cum[j+1]*q4.y + cum[j+2]*q4.z + cum[j+3]*q4.w;
            wv += hl[j+0]*q4.x  + hl[j+1]*q4.y  + hl[j+2]*q4.z  + hl[j+3]*q4.w;
        }
        g_u[base + lane] = u;
        g_w[base + lane] = wv;

        kreg = kN; qreg = qN; kureg = kuN; vs = vsN; vu = vuN; scv = scN;
        base = base2;
    }
    int mb = (chain * NC + c) * 1024 + lane * 32;
#pragma unroll
    for (int j = 0; j < 32; j += 4) {
        *(float4*)&g_cum[mb + j] = make_float4(cum[j], cum[j+1], cum[j+2], cum[j+3]);
        *(float4*)&g_loc[mb + j] = make_float4(hl[j],  hl[j+1],  hl[j+2],  hl[j+3]);
    }
}

// ---------------- 6. phase 2: fold chunks (smem-staged, prefetched) ---------
__global__ __launch_bounds__(1024) void phase2(const float* __restrict__ carry,
                                               float* __restrict__ outCarry) {
    __shared__ float cumS[2][1024];
    int chain = blockIdx.x;
    int tid = threadIdx.x;
    int j = tid & 31;
    float hreg = carry[chain * 1024 + tid];

    int mb0 = (chain * NC) * 1024;
    float cumNext = g_cum[mb0 + tid];
    float locNext = g_loc[mb0 + tid];

    for (int c = 0; c < NC; c++) {
        int s = c & 1;
        cumS[s][tid] = cumNext;
        float locCur = locNext;
        __syncthreads();
        if (c + 1 < NC) {
            int mb1 = (chain * NC + c + 1) * 1024;
            cumNext = g_cum[mb1 + tid];
            locNext = g_loc[mb1 + tid];
        }
        g_hinit[(chain * NC + c) * 1024 + tid] = hreg;   // state at chunk start
        float nv = locCur;
#pragma unroll
        for (int m = 0; m < 32; m++)
            nv += __shfl_sync(0xffffffffu, hreg, m) * cumS[s][m * 32 + j];
        hreg = nv;
    }
    outCarry[chain * 1024 + tid] = hreg;  // new_carry
}

// --------- 7. fused phase3 + rms + split: block per (b, chunk) ---------------
__global__ __launch_bounds__(512) void phase3_rms(const float* __restrict__ scale) {
    __shared__ float hin[NH][32 * 33];
    __shared__ float sscale[HID];
    __shared__ float partial[2][NH];
    int blk = blockIdx.x;            // b*NC + c
    int b = blk >> 5, c = blk & 31;
    int tid = threadIdx.x;
    int wid = tid >> 5, lane = tid & 31;
    int h = wid & 7, half = wid >> 3;

    for (int idx = tid; idx < NH * 1024; idx += 512) {
        int hh = idx >> 10, e = idx & 1023;
        int i = e >> 5, jj = e & 31;
        hin[hh][i * 33 + jj] = g_hinit[(((b * NH + hh) * NC) + c) * 1024 + e];
    }
    if (tid < HID) sscale[tid] = scale[tid];
    __syncthreads();

    for (int it = 0; it < 32; it++) {
        int t = c * CHUNK + half * 32 + it;
        int bsrow = b * NS + t;
        int base = (bsrow * NH + h) * 32;
        float ul  = g_u[base + lane];
        float acc = g_w[base + lane];
#pragma unroll
        for (int j = 0; j < 32; j++)
            acc += hin[h][lane * 33 + j] * __shfl_sync(0xffffffffu, ul, j);

        float ss = acc * acc;
#pragma unroll
        for (int o = 16; o > 0; o >>= 1) ss += __shfl_xor_sync(0xffffffffu, ss, o);
        if (lane == 0) partial[half][h] = ss;
        __syncthreads();
        float tot = partial[half][0] + partial[half][1] + partial[half][2] + partial[half][3]
                  + partial[half][4] + partial[half][5] + partial[half][6] + partial[half][7];
        float inv = rsqrtf(tot * (1.f / 256.f) + EPSF);
        float o = acc * inv * sscale[h * 32 + lane];
        __nv_bfloat16 hv = __float2bfloat16(o);
        int oidx = bsrow * HID + h * 32 + lane;
        g_o2h[oidx] = hv;
        g_o2l[oidx] = __float2bfloat16(o - __bfloat162float(hv));
        __syncthreads();
    }
}

// ---------------- launcher ---------------------------------------------------
extern "C" void kernel_launch(void* const* d_in, const int* in_sizes, int n_in,
                              void* d_out, int out_size) {
    const float* x      = (const float*)d_in[0];
    const float* action = (const float*)d_in[1];
    const float* mask   = (const float*)d_in[2];
    const float* carry  = (const float*)d_in[3];
    const float* Wq     = (const float*)d_in[4];
    const float* Wk     = (const float*)d_in[5];
    const float* Wv     = (const float*)d_in[6];
    const float* Wbeta  = (const float*)d_in[7];
    const float* Walpha = (const float*)d_in[8];
    const float* Wku    = (const float*)d_in[9];
    const float* Wvu    = (const float*)d_in[10];
    const float* Wgamma = (const float*)d_in[11];
    const float* rmssc  = (const float*)d_in[12];
    const float* Wout   = (const float*)d_in[13];
    const float* bout   = (const float*)d_in[14];

    float* outCarry = (float*)d_out;                       // (B,H,D,D) = 32768
    float* y        = (float*)d_out + NB * NH * ND * ND;   // (B,S,F)

    cudaFuncSetAttribute(gemm1_tc, cudaFuncAttributeMaxDynamicSharedMemorySize, SMEM_TOTAL);
    cudaFuncSetAttribute(gemm2_tc, cudaFuncAttributeMaxDynamicSharedMemorySize, SMEM_TOTAL);

    int nprep = N1ELEM + N2ELEM + N3ELEM + NH * ACTF;
    prep_weights<<<(nprep + 255) / 256, 256>>>(Wq, Wk, Wv, Wbeta, Walpha, Wout,
                                               Wku, Wvu, Wgamma);
    split_x<<<(ROWS * NF / 4) / 256, 256>>>(x);

    dim3 g1(NP1 / 128, ROWS / 128);       // (7, 64)
    gemm1_tc<<<g1, 256, SMEM_TOTAL>>>();

    act_kernel<<<(ROWS * NH * 32) / 256, 256>>>(mask, action);

    phase1<<<256, 128>>>();
    phase2<<<32, 1024>>>(carry, outCarry);
    phase3_rms<<<NB * NC, 512>>>(rmssc);

    dim3 g2(NF / 128, ROWS / 128);        // (4, 64)
    gemm2_tc<<<g2, 256, SMEM_TOTAL>>>(bout, y);
}

// round 8
// speedup vs baseline: 1.1817x; 1.0573x over previous
#include <cuda_runtime.h>
#include <cuda_bf16.h>
#include <cstdint>

// Problem constants
#define NB 4
#define NS 2048
#define NF 512
#define NH 8
#define ND 32
#define HID 256
#define ACTF 16
#define ROWS (NB*NS)          // 8192
#define NP1 896               // padded x-proj output width
#define NC 32                 // chunks per sequence
#define CHUNK 64              // NS / NC
#define EPSF 1e-6f

// ---------------- scratch (static device globals; no allocations) ----------
__device__ __nv_bfloat16 g_Bt1h[NP1*NF];   // [896,512] W1^T hi
__device__ __nv_bfloat16 g_Bt1l[NP1*NF];
__device__ __nv_bfloat16 g_Bt2h[NF*HID];   // [512,256] Wout^T hi
__device__ __nv_bfloat16 g_Bt2l[NF*HID];
__device__ __nv_bfloat16 g_xh[ROWS*NF];    // split x
__device__ __nv_bfloat16 g_xl[ROWS*NF];
__device__ __nv_bfloat16 g_o2h[ROWS*HID];  // split rms output (GEMM2 A)
__device__ __nv_bfloat16 g_o2l[ROWS*HID];
__device__ float g_proj[ROWS*NP1];
__device__ float g_qn[ROWS*HID];
__device__ float g_kn[ROWS*HID];
__device__ float g_kun[ROWS*HID];
__device__ float g_vs[ROWS*HID];
__device__ float g_vu[ROWS*HID];
__device__ float g_sc[ROWS*NH*4];        // beta, Aeff, Bg, ku.k
__device__ float g_u[ROWS*HID];
__device__ float g_w[ROWS*HID];
__device__ float g_cum[32*NC*ND*ND];
__device__ float g_loc[32*NC*ND*ND];
__device__ float g_hinit[32*NC*ND*ND];

__device__ __forceinline__ float sigm(float z) { return 1.f / (1.f + __expf(-z)); }

__device__ __forceinline__ uint32_t smem_to_u32(const void* smem_ptr) {
    uint32_t addr;
    asm("{ .reg .u64 tmp; cvta.to.shared.u64 tmp, %1; cvt.u32.u64 %0, tmp; }"
        : "=r"(addr) : "l"(smem_ptr));
    return addr;
}
__device__ __forceinline__ void ldsm_x4(uint32_t* r, uint32_t addr) {
    asm volatile("ldmatrix.sync.aligned.m8n8.x4.shared.b16 {%0,%1,%2,%3}, [%4];"
        : "=r"(r[0]), "=r"(r[1]), "=r"(r[2]), "=r"(r[3]) : "r"(addr));
}
__device__ __forceinline__ void mma16816(float* d, const uint32_t* a, const uint32_t* b) {
    asm volatile(
        "mma.sync.aligned.m16n8k16.row.col.f32.bf16.bf16.f32 "
        "{%0,%1,%2,%3}, {%4,%5,%6,%7}, {%8,%9}, {%0,%1,%2,%3};"
        : "+f"(d[0]), "+f"(d[1]), "+f"(d[2]), "+f"(d[3])
        : "r"(a[0]), "r"(a[1]), "r"(a[2]), "r"(a[3]), "r"(b[0]), "r"(b[1]));
}
__device__ __forceinline__ void cp16(uint32_t saddr, const void* gaddr) {
    asm volatile("cp.async.cg.shared.global [%0], [%1], 16;" :: "r"(saddr), "l"(gaddr));
}
__device__ __forceinline__ void cp_commit() {
    asm volatile("cp.async.commit_group;" ::: "memory");
}
__device__ __forceinline__ void cp_wait0() {
    asm volatile("cp.async.wait_group 0;" ::: "memory");
}
__device__ __forceinline__ uint32_t pack_bf16(float x, float y) {
    __nv_bfloat16 hx = __float2bfloat16(x), hy = __float2bfloat16(y);
    return ((uint32_t)__bfloat16_as_ushort(hy) << 16) | __bfloat16_as_ushort(hx);
}

// ---------------- 1. weight prep ---------------------------------------------
#define N1ELEM (NP1*NF)
#define N2ELEM (NF*HID)
__global__ void prep_weights(const float* __restrict__ Wq, const float* __restrict__ Wk,
                             const float* __restrict__ Wv, const float* __restrict__ Wb,
                             const float* __restrict__ Wa, const float* __restrict__ Wout) {
    int i = blockIdx.x * blockDim.x + threadIdx.x;
    if (i < N1ELEM) {
        int n = i >> 9, k = i & 511;          // Bt1[n,k] = W1[k,n]
        float v = 0.f;
        if (n < 256)       v = Wq[k*256 + n];
        else if (n < 512)  v = Wk[k*256 + n - 256];
        else if (n < 768)  v = Wv[k*256 + n - 512];
        else if (n < 776)  v = Wb[k*8 + n - 768];
        else if (n < 784)  v = Wa[k*8 + n - 776];
        __nv_bfloat16 h = __float2bfloat16(v);
        g_Bt1h[i] = h;
        g_Bt1l[i] = __float2bfloat16(v - __bfloat162float(h));
    } else if (i < N1ELEM + N2ELEM) {
        int j = i - N1ELEM;
        int n = j >> 8, k = j & 255;          // Bt2[n,k] = Wout[k,n]
        float v = Wout[k*512 + n];
        __nv_bfloat16 h = __float2bfloat16(v);
        g_Bt2h[j] = h;
        g_Bt2l[j] = __float2bfloat16(v - __bfloat162float(h));
    }
}

// ---------------- 1b. split x into hi/lo bf16 -------------------------------
__global__ __launch_bounds__(256) void split_x(const float* __restrict__ x) {
    int i = blockIdx.x * blockDim.x + threadIdx.x;   // float4 index
    float4 v = *(const float4*)(x + i * 4);
    __nv_bfloat16 h0 = __float2bfloat16(v.x), h1 = __float2bfloat16(v.y);
    __nv_bfloat16 h2 = __float2bfloat16(v.z), h3 = __float2bfloat16(v.w);
    uint2 hp, lp;
    hp.x = ((uint32_t)__bfloat16_as_ushort(h1) << 16) | __bfloat16_as_ushort(h0);
    hp.y = ((uint32_t)__bfloat16_as_ushort(h3) << 16) | __bfloat16_as_ushort(h2);
    lp.x = pack_bf16(v.x - __bfloat162float(h0), v.y - __bfloat162float(h1));
    lp.y = pack_bf16(v.z - __bfloat162float(h2), v.w - __bfloat162float(h3));
    *(uint2*)(g_xh + i * 4) = hp;
    *(uint2*)(g_xl + i * 4) = lp;
}

// ---------------- 2. HMMA split-bf16 GEMM ------------------------------------
// A register-staged, B via cp.async; 2 CTAs/SM. Tile 128x128, BK=32.
#define ROWB 80                 // padded smem row stride (bytes)
#define OAH 0
#define OAL 10240
#define OBH 20480
#define OBL 30720
#define STG 40960
#define SMEM_TOTAL (2*STG)

__device__ __forceinline__ void gemm_hmma(const __nv_bfloat16* __restrict__ Ah,
                                          const __nv_bfloat16* __restrict__ Al,
                                          const __nv_bfloat16* __restrict__ Bh,
                                          const __nv_bfloat16* __restrict__ Bl,
                                          float* __restrict__ C,
                                          const float* __restrict__ bias,
                                          int N, int K) {
    extern __shared__ char smem[];
    uint32_t sb = smem_to_u32(smem);
    int tid = threadIdx.x, lane = tid & 31, wid = tid >> 5;
    int m0 = blockIdx.y * 128, n0 = blockIdx.x * 128;
    int wm = (wid >> 2) * 64, wn = (wid & 3) * 32;

    uint32_t aOff = (uint32_t)((wm + (lane & 7) + ((lane >> 3) & 1) * 8) * ROWB
                               + ((lane >> 4) * 8) * 2);
    uint32_t bOff = (uint32_t)((wn + (lane & 7) + ((lane >> 4) & 1) * 8) * ROWB
                               + (((lane >> 3) & 1) * 8) * 2);

    float acc[4][4][4];
#pragma unroll
    for (int mt = 0; mt < 4; mt++)
#pragma unroll
        for (int nt = 0; nt < 4; nt++)
#pragma unroll
            for (int e = 0; e < 4; e++) acc[mt][nt][e] = 0.f;

    int crow = tid >> 1;
    int cel = (tid & 1) * 16;
    uint32_t sOff = (uint32_t)(crow * ROWB + (tid & 1) * 32);
    const __nv_bfloat16* pAh = Ah + (size_t)(m0 + crow) * K + cel;
    const __nv_bfloat16* pAl = Al + (size_t)(m0 + crow) * K + cel;
    const __nv_bfloat16* pBh = Bh + (size_t)(n0 + crow) * K + cel;
    const __nv_bfloat16* pBl = Bl + (size_t)(n0 + crow) * K + cel;
    int nkc = K >> 5;

    uint4 rAh[2], rAl[2];
#define LOAD_A(kc) do {                                                 \
        int _ko = (kc) * 32;                                            \
        rAh[0] = *(const uint4*)(pAh + _ko); rAh[1] = *(const uint4*)(pAh + _ko + 8); \
        rAl[0] = *(const uint4*)(pAl + _ko); rAl[1] = *(const uint4*)(pAl + _ko + 8); \
    } while(0)
#define STORE_A(s) do {                                                 \
        char* _st = smem + (s) * STG;                                   \
        *(uint4*)(_st + OAH + sOff) = rAh[0]; *(uint4*)(_st + OAH + sOff + 16) = rAh[1]; \
        *(uint4*)(_st + OAL + sOff) = rAl[0]; *(uint4*)(_st + OAL + sOff + 16) = rAl[1]; \
    } while(0)
#define CP_B(kc, s) do {                                                \
        uint32_t _stb = sb + (s) * STG;                                 \
        int _ko = (kc) * 32;                                            \
        cp16(_stb + OBH + sOff,      pBh + _ko);                        \
        cp16(_stb + OBH + sOff + 16, pBh + _ko + 8);                    \
        cp16(_stb + OBL + sOff,      pBl + _ko);                        \
        cp16(_stb + OBL + sOff + 16, pBl + _ko + 8);                    \
    } while(0)

    LOAD_A(0);
    CP_B(0, 0);
    cp_commit();
    STORE_A(0);
    cp_wait0();
    __syncthreads();

    for (int kc = 0; kc < nkc; kc++) {
        bool more = (kc + 1 < nkc);
        int s = kc & 1;
        if (more) {
            LOAD_A(kc + 1);
            CP_B(kc + 1, s ^ 1);
        }
        cp_commit();

        uint32_t stb = sb + s * STG;
#pragma unroll
        for (int ks = 0; ks < 2; ks++) {
            uint32_t kb = ks * 32;
            uint32_t af[4][4], bhF[2][4], blF[2][4];
#pragma unroll
            for (int mt = 0; mt < 4; mt++)
                ldsm_x4(af[mt], stb + OAH + aOff + mt * (16 * ROWB) + kb);
#pragma unroll
            for (int np = 0; np < 2; np++) {
                ldsm_x4(bhF[np], stb + OBH + bOff + np * (16 * ROWB) + kb);
                ldsm_x4(blF[np], stb + OBL + bOff + np * (16 * ROWB) + kb);
            }
#pragma unroll
            for (int mt = 0; mt < 4; mt++)
#pragma unroll
                for (int nt = 0; nt < 4; nt++)
                    mma16816(acc[mt][nt], af[mt], &bhF[nt >> 1][(nt & 1) * 2]);
#pragma unroll
            for (int mt = 0; mt < 4; mt++)
#pragma unroll
                for (int nt = 0; nt < 4; nt++)
                    mma16816(acc[mt][nt], af[mt], &blF[nt >> 1][(nt & 1) * 2]);
#pragma unroll
            for (int mt = 0; mt < 4; mt++)
                ldsm_x4(af[mt], stb + OAL + aOff + mt * (16 * ROWB) + kb);
#pragma unroll
            for (int mt = 0; mt < 4; mt++)
#pragma unroll
                for (int nt = 0; nt < 4; nt++)
                    mma16816(acc[mt][nt], af[mt], &bhF[nt >> 1][(nt & 1) * 2]);
        }
        __syncthreads();
        if (more) {
            STORE_A(s ^ 1);
            cp_wait0();
        }
        __syncthreads();
    }
#undef LOAD_A
#undef STORE_A
#undef CP_B

    // epilogue
#pragma unroll
    for (int mt = 0; mt < 4; mt++) {
        int r0 = m0 + wm + mt * 16 + (lane >> 2);
#pragma unroll
        for (int nt = 0; nt < 4; nt++) {
            int col = n0 + wn + nt * 8 + (lane & 3) * 2;
            float b0 = 0.f, b1 = 0.f;
            if (bias) { b0 = bias[col]; b1 = bias[col + 1]; }
            float2 v0, v1;
            v0.x = acc[mt][nt][0] + b0; v0.y = acc[mt][nt][1] + b1;
            v1.x = acc[mt][nt][2] + b0; v1.y = acc[mt][nt][3] + b1;
            *(float2*)(C + (size_t)r0 * N + col) = v0;
            *(float2*)(C + (size_t)(r0 + 8) * N + col) = v1;
        }
    }
}

__global__ __launch_bounds__(256, 2) void gemm1_tc() {
    gemm_hmma(g_xh, g_xl, g_Bt1h, g_Bt1l, g_proj, nullptr, NP1, NF);
}
__global__ __launch_bounds__(256, 2) void gemm2_tc(const float* __restrict__ bout,
                                                   float* __restrict__ y) {
    gemm_hmma(g_o2h, g_o2l, g_Bt2h, g_Bt2l, y, bout, NF, HID);
}

// ------- 3. activations + l2norm + fused action proj (coalesced weights) ----
__global__ __launch_bounds__(256) void act_kernel(const float* __restrict__ mask,
                                                  const float* __restrict__ action,
                                                  const float* __restrict__ Wku,
                                                  const float* __restrict__ Wvu,
                                                  const float* __restrict__ Wg) {
    int w = (blockIdx.x * blockDim.x + threadIdx.x) >> 5;   // (b*S+s)*H + h
    int lane = threadIdx.x & 31;
    if (w >= ROWS * NH) return;
    int bs = w >> 3, h = w & 7;
    int pb = bs * NP1;

    // action row: 4 broadcast float4 loads (all lanes same address, N=1)
    const float4* ar4 = (const float4*)(action + bs * ACTF);
    float4 a0 = ar4[0], a1 = ar4[1], a2 = ar4[2], a3 = ar4[3];
    float a[ACTF] = { a0.x,a0.y,a0.z,a0.w, a1.x,a1.y,a1.z,a1.w,
                      a2.x,a2.y,a2.z,a2.w, a3.x,a3.y,a3.z,a3.w };

    // weights original layout [ACTF][HID]: lanes contiguous -> 1 wavefront/LDG
    int c = h * 32 + lane;
    float kur = 0.f, vur = 0.f, gr = 0.f;
#pragma unroll
    for (int k2 = 0; k2 < ACTF; k2++) {
        kur += a[k2] * Wku[k2 * HID + c];
        vur += a[k2] * Wvu[k2 * HID + c];
        gr  += a[k2] * Wg[k2 * NH + h];     // broadcast (512B table, L1-hit)
    }

    float qr  = g_proj[pb + h*32 + lane];
    float kr  = g_proj[pb + 256 + h*32 + lane];
    float vr  = g_proj[pb + 512 + h*32 + lane];

    float q  = qr * sigm(qr);
    float k  = kr * sigm(kr);
    float ku = kur * sigm(kur);

    float sq = q*q, sk = k*k, sku = ku*ku;
#pragma unroll
    for (int o = 16; o > 0; o >>= 1) {
        sq  += __shfl_xor_sync(0xffffffffu, sq,  o);
        sk  += __shfl_xor_sync(0xffffffffu, sk,  o);
        sku += __shfl_xor_sync(0xffffffffu, sku, o);
    }
    q  *= rsqrtf(sq  + EPSF);
    k  *= rsqrtf(sk  + EPSF);
    ku *= rsqrtf(sku + EPSF);

    float dk = ku * k;
#pragma unroll
    for (int o = 16; o > 0; o >>= 1) dk += __shfl_xor_sync(0xffffffffu, dk, o);

    int base = w * 32;
    g_qn[base + lane]  = q;
    g_kn[base + lane]  = k;
    g_kun[base + lane] = ku;
    g_vs[base + lane]  = vr;
    g_vu[base + lane]  = vur;
    if (lane == 0) {
        float br = g_proj[pb + 768 + h];
        float ar = g_proj[pb + 776 + h];
        float m  = mask[bs];
        g_sc[w*4 + 0] = sigm(br);                 // beta
        g_sc[w*4 + 1] = sigm(ar) * (1.f - m);     // Aeff
        g_sc[w*4 + 2] = sigm(gr);                 // Bg
        g_sc[w*4 + 3] = dk;                       // ku . k
    }
}

// ---------------- 5. phase 1: chunked scan, smem-broadcast operands ---------
__global__ __launch_bounds__(128) void phase1() {
    __shared__ float sk[4][32], sq[4][32], sku[4][32];
    int wq = threadIdx.x >> 5;
    int wg = blockIdx.x * 4 + wq;                   // 0..1023
    int lane = threadIdx.x & 31;
    int chain = wg >> 5;        // b*8+h
    int c = wg & 31;
    int b = chain >> 3, h = chain & 7;

    float cum[32], hl[32];
#pragma unroll
    for (int j = 0; j < 32; j++) { cum[j] = (j == lane) ? 1.f : 0.f; hl[j] = 0.f; }

    int t0 = c * CHUNK;
    int base = ((b * NS + t0) * NH + h) * 32;
    float kreg  = g_kn[base + lane];
    float qreg  = g_qn[base + lane];
    float kureg = g_kun[base + lane];
    float vs    = g_vs[base + lane];
    float vu    = g_vu[base + lane];
    float4 scv  = *(const float4*)&g_sc[((b * NS + t0) * NH + h) * 4];

    for (int t = t0; t < t0 + CHUNK; t++) {
        __syncwarp();
        sk[wq][lane]  = kreg;
        sq[wq][lane]  = qreg;
        sku[wq][lane] = kureg;
        __syncwarp();

        // prefetch next timestep
        float kN = 0.f, qN = 0.f, kuN = 0.f, vsN = 0.f, vuN = 0.f;
        float4 scN = scv;
        int base2 = base;
        if (t + 1 < t0 + CHUNK) {
            int w2 = (b * NS + t + 1) * NH + h;
            base2 = w2 * 32;
            kN  = g_kn[base2 + lane];
            qN  = g_qn[base2 + lane];
            kuN = g_kun[base2 + lane];
            vsN = g_vs[base2 + lane];
            vuN = g_vu[base2 + lane];
            scN = *(const float4*)&g_sc[w2 * 4];
        }

        float beta = scv.x, Ae = scv.y, Bg = scv.z, kuk = scv.w;
        float ck = 0.f, hk = 0.f;
#pragma unroll
        for (int j4 = 0; j4 < 8; j4++) {
            float4 k4 = *(const float4*)&sk[wq][j4 * 4];
            ck += cum[j4*4+0]*k4.x + cum[j4*4+1]*k4.y + cum[j4*4+2]*k4.z + cum[j4*4+3]*k4.w;
            hk += hl[j4*4+0]*k4.x  + hl[j4*4+1]*k4.y  + hl[j4*4+2]*k4.z  + hl[j4*4+3]*k4.w;
        }
        float e  = Ae * beta * ck;
        float cc = beta * vs - Ae * beta * hk - Bg * beta * kuk * vu;
        float dd = Bg * vu;

        float u = 0.f, wv = 0.f;
#pragma unroll
        for (int j4 = 0; j4 < 8; j4++) {
            float4 k4  = *(const float4*)&sk[wq][j4 * 4];
            float4 ku4 = *(const float4*)&sku[wq][j4 * 4];
            float4 q4  = *(const float4*)&sq[wq][j4 * 4];
            int j = j4 * 4;
            cum[j+0] = Ae * cum[j+0] - e * k4.x;
            cum[j+1] = Ae * cum[j+1] - e * k4.y;
            cum[j+2] = Ae * cum[j+2] - e * k4.z;
            cum[j+3] = Ae * cum[j+3] - e * k4.w;
            hl[j+0] = Ae * hl[j+0] + cc * k4.x + dd * ku4.x;
            hl[j+1] = Ae * hl[j+1] + cc * k4.y + dd * ku4.y;
            hl[j+2] = Ae * hl[j+2] + cc * k4.z + dd * ku4.z;
            hl[j+3] = Ae * hl[j+3] + cc * k4.w + dd * ku4.w;
            u  += cum[j+0]*q4.x + cum[j+1]*q4.y + cum[j+2]*q4.z + cum[j+3]*q4.w;
            wv += hl[j+0]*q4.x  + hl[j+1]*q4.y  + hl[j+2]*q4.z  + hl[j+3]*q4.w;
        }
        g_u[base + lane] = u;
        g_w[base + lane] = wv;

        kreg = kN; qreg = qN; kureg = kuN; vs = vsN; vu = vuN; scv = scN;
        base = base2;
    }
    int mb = (chain * NC + c) * 1024 + lane * 32;
#pragma unroll
    for (int j = 0; j < 32; j += 4) {
        *(float4*)&g_cum[mb + j] = make_float4(cum[j], cum[j+1], cum[j+2], cum[j+3]);
        *(float4*)&g_loc[mb + j] = make_float4(hl[j],  hl[j+1],  hl[j+2],  hl[j+3]);
    }
}

// ---------------- 6. phase 2: fold chunks (smem-staged, prefetched) ---------
__global__ __launch_bounds__(1024) void phase2(const float* __restrict__ carry,
                                               float* __restrict__ outCarry) {
    __shared__ float cumS[2][1024];
    int chain = blockIdx.x;
    int tid = threadIdx.x;
    int j = tid & 31;
    float hreg = carry[chain * 1024 + tid];

    int mb0 = (chain * NC) * 1024;
    float cumNext = g_cum[mb0 + tid];
    float locNext = g_loc[mb0 + tid];

    for (int c = 0; c < NC; c++) {
        int s = c & 1;
        cumS[s][tid] = cumNext;
        float locCur = locNext;
        __syncthreads();
        if (c + 1 < NC) {
            int mb1 = (chain * NC + c + 1) * 1024;
            cumNext = g_cum[mb1 + tid];
            locNext = g_loc[mb1 + tid];
        }
        g_hinit[(chain * NC + c) * 1024 + tid] = hreg;   // state at chunk start
        float nv = locCur;
#pragma unroll
        for (int m = 0; m < 32; m++)
            nv += __shfl_sync(0xffffffffu, hreg, m) * cumS[s][m * 32 + j];
        hreg = nv;
    }
    outCarry[chain * 1024 + tid] = hreg;  // new_carry
}

// --------- 7. fused phase3 + rms + split: block per (b, chunk) ---------------
__global__ __launch_bounds__(512) void phase3_rms(const float* __restrict__ scale) {
    __shared__ float hin[NH][32 * 33];
    __shared__ float sscale[HID];
    __shared__ float partial[2][NH];
    int blk = blockIdx.x;            // b*NC + c
    int b = blk >> 5, c = blk & 31;
    int tid = threadIdx.x;
    int wid = tid >> 5, lane = tid & 31;
    int h = wid & 7, half = wid >> 3;

    for (int idx = tid; idx < NH * 1024; idx += 512) {
        int hh = idx >> 10, e = idx & 1023;
        int i = e >> 5, jj = e & 31;
        hin[hh][i * 33 + jj] = g_hinit[(((b * NH + hh) * NC) + c) * 1024 + e];
    }
    if (tid < HID) sscale[tid] = scale[tid];
    __syncthreads();

    for (int it = 0; it < 32; it++) {
        int t = c * CHUNK + half * 32 + it;
        int bsrow = b * NS + t;
        int base = (bsrow * NH + h) * 32;
        float ul  = g_u[base + lane];
        float acc = g_w[base + lane];
#pragma unroll
        for (int j = 0; j < 32; j++)
            acc += hin[h][lane * 33 + j] * __shfl_sync(0xffffffffu, ul, j);

        float ss = acc * acc;
#pragma unroll
        for (int o = 16; o > 0; o >>= 1) ss += __shfl_xor_sync(0xffffffffu, ss, o);
        if (lane == 0) partial[half][h] = ss;
        __syncthreads();
        float tot = partial[half][0] + partial[half][1] + partial[half][2] + partial[half][3]
                  + partial[half][4] + partial[half][5] + partial[half][6] + partial[half][7];
        float inv = rsqrtf(tot * (1.f / 256.f) + EPSF);
        float o = acc * inv * sscale[h * 32 + lane];
        __nv_bfloat16 hv = __float2bfloat16(o);
        int oidx = bsrow * HID + h * 32 + lane;
        g_o2h[oidx] = hv;
        g_o2l[oidx] = __float2bfloat16(o - __bfloat162float(hv));
        __syncthreads();
    }
}

// ---------------- launcher ---------------------------------------------------
extern "C" void kernel_launch(void* const* d_in, const int* in_sizes, int n_in,
                              void* d_out, int out_size) {
    const float* x      = (const float*)d_in[0];
    const float* action = (const float*)d_in[1];
    const float* mask   = (const float*)d_in[2];
    const float* carry  = (const float*)d_in[3];
    const float* Wq     = (const float*)d_in[4];
    const float* Wk     = (const float*)d_in[5];
    const float* Wv     = (const float*)d_in[6];
    const float* Wbeta  = (const float*)d_in[7];
    const float* Walpha = (const float*)d_in[8];
    const float* Wku    = (const float*)d_in[9];
    const float* Wvu    = (const float*)d_in[10];
    const float* Wgamma = (const float*)d_in[11];
    const float* rmssc  = (const float*)d_in[12];
    const float* Wout   = (const float*)d_in[13];
    const float* bout   = (const float*)d_in[14];

    float* outCarry = (float*)d_out;                       // (B,H,D,D) = 32768
    float* y        = (float*)d_out + NB * NH * ND * ND;   // (B,S,F)

    cudaFuncSetAttribute(gemm1_tc, cudaFuncAttributeMaxDynamicSharedMemorySize, SMEM_TOTAL);
    cudaFuncSetAttribute(gemm2_tc, cudaFuncAttributeMaxDynamicSharedMemorySize, SMEM_TOTAL);

    int nprep = N1ELEM + N2ELEM;
    prep_weights<<<(nprep + 255) / 256, 256>>>(Wq, Wk, Wv, Wbeta, Walpha, Wout);
    split_x<<<(ROWS * NF / 4) / 256, 256>>>(x);

    dim3 g1(NP1 / 128, ROWS / 128);       // (7, 64)
    gemm1_tc<<<g1, 256, SMEM_TOTAL>>>();

    act_kernel<<<(ROWS * NH * 32) / 256, 256>>>(mask, action, Wku, Wvu, Wgamma);

    phase1<<<256, 128>>>();
    phase2<<<32, 1024>>>(carry, outCarry);
    phase3_rms<<<NB * NC, 512>>>(rmssc);

    dim3 g2(NF / 128, ROWS / 128);        // (4, 64)
    gemm2_tc<<<g2, 256, SMEM_TOTAL>>>(bout, y);
}

// round 9
// speedup vs baseline: 1.2249x; 1.0366x over previous
#include <cuda_runtime.h>
#include <cuda_fp16.h>
#include <cstdint>

// Problem constants
#define NB 4
#define NS 2048
#define NF 512
#define NH 8
#define ND 32
#define HID 256
#define ACTF 16
#define ROWS (NB*NS)          // 8192
#define NP1 768               // x-proj output width (q,k,v only)
#define NC 32                 // chunks per sequence
#define CHUNK 64              // NS / NC
#define EPSF 1e-6f
#define BSCALE 32.0f
#define BUNSCALE 0.03125f

// ---------------- scratch (static device globals; no allocations) ----------
__device__ __half g_Bt1h[NP1*NF];   // [768,512] W1^T hi (x32)
__device__ __half g_Bt1l[NP1*NF];   // lo
__device__ __half g_Bt2h[NF*HID];   // [512,256] Wout^T hi (x32)
__device__ __half g_Bt2l[NF*HID];
__device__ __half g_xh[ROWS*NF];    // x as fp16 (hi only)
__device__ __half g_o2h[ROWS*HID];  // rms output fp16 (GEMM2 A)
__device__ float g_WbaT[16*NF];     // transposed beta/alpha weights
__device__ float g_ba[ROWS*16];     // beta/alpha raw projections
__device__ float g_proj[ROWS*NP1];
__device__ float g_qn[ROWS*HID];
__device__ float g_kn[ROWS*HID];
__device__ float g_kun[ROWS*HID];
__device__ float g_vu[ROWS*HID];
__device__ float g_sc[ROWS*NH*4];   // beta, Aeff, Bg, ku.k
__device__ float g_u[ROWS*HID];
__device__ float g_w[ROWS*HID];
__device__ float g_cum[32*NC*ND*ND];
__device__ float g_loc[32*NC*ND*ND];
__device__ float g_hinit[32*NC*ND*ND];

__device__ __forceinline__ float sigm(float z) { return 1.f / (1.f + __expf(-z)); }

__device__ __forceinline__ uint32_t smem_to_u32(const void* smem_ptr) {
    uint32_t addr;
    asm("{ .reg .u64 tmp; cvta.to.shared.u64 tmp, %1; cvt.u32.u64 %0, tmp; }"
        : "=r"(addr) : "l"(smem_ptr));
    return addr;
}
__device__ __forceinline__ void ldsm_x4(uint32_t* r, uint32_t addr) {
    asm volatile("ldmatrix.sync.aligned.m8n8.x4.shared.b16 {%0,%1,%2,%3}, [%4];"
        : "=r"(r[0]), "=r"(r[1]), "=r"(r[2]), "=r"(r[3]) : "r"(addr));
}
__device__ __forceinline__ void mma16816(float* d, const uint32_t* a, const uint32_t* b) {
    asm volatile(
        "mma.sync.aligned.m16n8k16.row.col.f32.f16.f16.f32 "
        "{%0,%1,%2,%3}, {%4,%5,%6,%7}, {%8,%9}, {%0,%1,%2,%3};"
        : "+f"(d[0]), "+f"(d[1]), "+f"(d[2]), "+f"(d[3])
        : "r"(a[0]), "r"(a[1]), "r"(a[2]), "r"(a[3]), "r"(b[0]), "r"(b[1]));
}
__device__ __forceinline__ void cp16(uint32_t saddr, const void* gaddr) {
    asm volatile("cp.async.cg.shared.global [%0], [%1], 16;" :: "r"(saddr), "l"(gaddr));
}
__device__ __forceinline__ void cp_commit() {
    asm volatile("cp.async.commit_group;" ::: "memory");
}
__device__ __forceinline__ void cp_wait0() {
    asm volatile("cp.async.wait_group 0;" ::: "memory");
}

// ---------------- 1. weight prep ---------------------------------------------
#define N1ELEM (NP1*NF)
#define N2ELEM (NF*HID)
#define N3ELEM (16*NF)
__global__ void prep_weights(const float* __restrict__ Wq, const float* __restrict__ Wk,
                             const float* __restrict__ Wv, const float* __restrict__ Wb,
                             const float* __restrict__ Wa, const float* __restrict__ Wout) {
    int i = blockIdx.x * blockDim.x + threadIdx.x;
    if (i < N1ELEM) {
        int n = i >> 9, k = i & 511;          // Bt1[n,k] = W1[k,n] * 32
        float v;
        if (n < 256)       v = Wq[k*256 + n];
        else if (n < 512)  v = Wk[k*256 + n - 256];
        else               v = Wv[k*256 + n - 512];
        v *= BSCALE;
        __half h = __float2half_rn(v);
        g_Bt1h[i] = h;
        g_Bt1l[i] = __float2half_rn(v - __half2float(h));
    } else if (i < N1ELEM + N2ELEM) {
        int j = i - N1ELEM;
        int n = j >> 8, k = j & 255;          // Bt2[n,k] = Wout[k,n] * 32
        float v = Wout[k*512 + n] * BSCALE;
        __half h = __float2half_rn(v);
        g_Bt2h[j] = h;
        g_Bt2l[j] = __float2half_rn(v - __half2float(h));
    } else if (i < N1ELEM + N2ELEM + N3ELEM) {
        int j = i - N1ELEM - N2ELEM;
        int jj = j >> 9, k = j & 511;         // WbaT[jj][k]
        g_WbaT[j] = (jj < 8) ? Wb[k*8 + jj] : Wa[k*8 + (jj - 8)];
    }
}

// ---------------- 1b. x -> fp16 (hi only) -----------------------------------
__global__ __launch_bounds__(256) void split_x(const float* __restrict__ x) {
    int i = blockIdx.x * blockDim.x + threadIdx.x;   // float4 index
    float4 v = *(const float4*)(x + i * 4);
    __half2 p0 = __floats2half2_rn(v.x, v.y);
    __half2 p1 = __floats2half2_rn(v.z, v.w);
    uint2 hp;
    hp.x = *(uint32_t*)&p0;
    hp.y = *(uint32_t*)&p1;
    *(uint2*)(g_xh + i * 4) = hp;
}

// ---------------- 1c. beta/alpha: exact fp32 warp-per-row --------------------
__global__ __launch_bounds__(256) void balpha_kernel(const float* __restrict__ x) {
    int w = blockIdx.x * 8 + (threadIdx.x >> 5);     // bs row
    int lane = threadIdx.x & 31;
    const float* xr = x + (size_t)w * NF;
    float xreg[16];
#pragma unroll
    for (int i = 0; i < 16; i++) xreg[i] = xr[i * 32 + lane];
#pragma unroll
    for (int j = 0; j < 16; j++) {
        const float* wt = &g_WbaT[j * NF];
        float s = 0.f;
#pragma unroll
        for (int i = 0; i < 16; i++) s += xreg[i] * wt[i * 32 + lane];
#pragma unroll
        for (int o = 16; o > 0; o >>= 1) s += __shfl_xor_sync(0xffffffffu, s, o);
        if (lane == 0) g_ba[w * 16 + j] = s;
    }
}

// ---------------- 2. HMMA split-fp16 GEMM (2 products) -----------------------
// C = Ah(fp16) @ (Bh+Bl)(fp16,x32)^T * (1/32) (+bias). Tile 128x128, BK=32.
#define ROWB 80                 // padded smem row stride (bytes)
#define OAH 0
#define OBH 10240
#define OBL 20480
#define STG 30720
#define SMEM_TOTAL (2*STG)

__device__ __forceinline__ void gemm_hmma(const __half* __restrict__ Ah,
                                          const __half* __restrict__ Bh,
                                          const __half* __restrict__ Bl,
                                          float* __restrict__ C,
                                          const float* __restrict__ bias,
                                          int N, int K) {
    extern __shared__ char smem[];
    uint32_t sb = smem_to_u32(smem);
    int tid = threadIdx.x, lane = tid & 31, wid = tid >> 5;
    int m0 = blockIdx.y * 128, n0 = blockIdx.x * 128;
    int wm = (wid >> 2) * 64, wn = (wid & 3) * 32;

    uint32_t aOff = (uint32_t)((wm + (lane & 7) + ((lane >> 3) & 1) * 8) * ROWB
                               + ((lane >> 4) * 8) * 2);
    uint32_t bOff = (uint32_t)((wn + (lane & 7) + ((lane >> 4) & 1) * 8) * ROWB
                               + (((lane >> 3) & 1) * 8) * 2);

    float acc[4][4][4];
#pragma unroll
    for (int mt = 0; mt < 4; mt++)
#pragma unroll
        for (int nt = 0; nt < 4; nt++)
#pragma unroll
            for (int e = 0; e < 4; e++) acc[mt][nt][e] = 0.f;

    int crow = tid >> 1;
    int cel = (tid & 1) * 16;
    uint32_t sOff = (uint32_t)(crow * ROWB + (tid & 1) * 32);
    const __half* pAh = Ah + (size_t)(m0 + crow) * K + cel;
    const __half* pBh = Bh + (size_t)(n0 + crow) * K + cel;
    const __half* pBl = Bl + (size_t)(n0 + crow) * K + cel;
    int nkc = K >> 5;

    uint4 rAh[2];
#define LOAD_A(kc) do {                                                 \
        int _ko = (kc) * 32;                                            \
        rAh[0] = *(const uint4*)(pAh + _ko); rAh[1] = *(const uint4*)(pAh + _ko + 8); \
    } while(0)
#define STORE_A(s) do {                                                 \
        char* _st = smem + (s) * STG;                                   \
        *(uint4*)(_st + OAH + sOff) = rAh[0]; *(uint4*)(_st + OAH + sOff + 16) = rAh[1]; \
    } while(0)
#define CP_B(kc, s) do {                                                \
        uint32_t _stb = sb + (s) * STG;                                 \
        int _ko = (kc) * 32;                                            \
        cp16(_stb + OBH + sOff,      pBh + _ko);                        \
        cp16(_stb + OBH + sOff + 16, pBh + _ko + 8);                    \
        cp16(_stb + OBL + sOff,      pBl + _ko);                        \
        cp16(_stb + OBL + sOff + 16, pBl + _ko + 8);                    \
    } while(0)

    LOAD_A(0);
    CP_B(0, 0);
    cp_commit();
    STORE_A(0);
    cp_wait0();
    __syncthreads();

    for (int kc = 0; kc < nkc; kc++) {
        bool more = (kc + 1 < nkc);
        int s = kc & 1;
        if (more) {
            LOAD_A(kc + 1);
            CP_B(kc + 1, s ^ 1);
        }
        cp_commit();

        uint32_t stb = sb + s * STG;
#pragma unroll
        for (int ks = 0; ks < 2; ks++) {
            uint32_t kb = ks * 32;
            uint32_t af[4][4], bhF[2][4], blF[2][4];
#pragma unroll
            for (int mt = 0; mt < 4; mt++)
                ldsm_x4(af[mt], stb + OAH + aOff + mt * (16 * ROWB) + kb);
#pragma unroll
            for (int np = 0; np < 2; np++) {
                ldsm_x4(bhF[np], stb + OBH + bOff + np * (16 * ROWB) + kb);
                ldsm_x4(blF[np], stb + OBL + bOff + np * (16 * ROWB) + kb);
            }
#pragma unroll
            for (int mt = 0; mt < 4; mt++)
#pragma unroll
                for (int nt = 0; nt < 4; nt++)
                    mma16816(acc[mt][nt], af[mt], &bhF[nt >> 1][(nt & 1) * 2]);
#pragma unroll
            for (int mt = 0; mt < 4; mt++)
#pragma unroll
                for (int nt = 0; nt < 4; nt++)
                    mma16816(acc[mt][nt], af[mt], &blF[nt >> 1][(nt & 1) * 2]);
        }
        __syncthreads();
        if (more) {
            STORE_A(s ^ 1);
            cp_wait0();
        }
        __syncthreads();
    }
#undef LOAD_A
#undef STORE_A
#undef CP_B

    // epilogue: unscale by 1/32, then optional bias
#pragma unroll
    for (int mt = 0; mt < 4; mt++) {
        int r0 = m0 + wm + mt * 16 + (lane >> 2);
#pragma unroll
        for (int nt = 0; nt < 4; nt++) {
            int col = n0 + wn + nt * 8 + (lane & 3) * 2;
            float b0 = 0.f, b1 = 0.f;
            if (bias) { b0 = bias[col]; b1 = bias[col + 1]; }
            float2 v0, v1;
            v0.x = acc[mt][nt][0] * BUNSCALE + b0; v0.y = acc[mt][nt][1] * BUNSCALE + b1;
            v1.x = acc[mt][nt][2] * BUNSCALE + b0; v1.y = acc[mt][nt][3] * BUNSCALE + b1;
            *(float2*)(C + (size_t)r0 * N + col) = v0;
            *(float2*)(C + (size_t)(r0 + 8) * N + col) = v1;
        }
    }
}

__global__ __launch_bounds__(256, 2) void gemm1_tc() {
    gemm_hmma(g_xh, g_Bt1h, g_Bt1l, g_proj, nullptr, NP1, NF);
}
__global__ __launch_bounds__(256, 2) void gemm2_tc(const float* __restrict__ bout,
                                                   float* __restrict__ y) {
    gemm_hmma(g_o2h, g_Bt2h, g_Bt2l, y, bout, NF, HID);
}

// ------- 3. activations + l2norm + fused action proj (coalesced weights) ----
__global__ __launch_bounds__(256) void act_kernel(const float* __restrict__ mask,
                                                  const float* __restrict__ action,
                                                  const float* __restrict__ Wku,
                                                  const float* __restrict__ Wvu,
                                                  const float* __restrict__ Wg) {
    int w = (blockIdx.x * blockDim.x + threadIdx.x) >> 5;   // (b*S+s)*H + h
    int lane = threadIdx.x & 31;
    if (w >= ROWS * NH) return;
    int bs = w >> 3, h = w & 7;
    int pb = bs * NP1;

    // action row: 4 broadcast float4 loads
    const float4* ar4 = (const float4*)(action + bs * ACTF);
    float4 a0 = ar4[0], a1 = ar4[1], a2 = ar4[2], a3 = ar4[3];
    float a[ACTF] = { a0.x,a0.y,a0.z,a0.w, a1.x,a1.y,a1.z,a1.w,
                      a2.x,a2.y,a2.z,a2.w, a3.x,a3.y,a3.z,a3.w };

    int c = h * 32 + lane;
    float kur = 0.f, vur = 0.f, gr = 0.f;
#pragma unroll
    for (int k2 = 0; k2 < ACTF; k2++) {
        kur += a[k2] * Wku[k2 * HID + c];
        vur += a[k2] * Wvu[k2 * HID + c];
        gr  += a[k2] * Wg[k2 * NH + h];
    }

    float qr  = g_proj[pb + h*32 + lane];
    float kr  = g_proj[pb + 256 + h*32 + lane];

    float q  = qr * sigm(qr);
    float k  = kr * sigm(kr);
    float ku = kur * sigm(kur);

    float sq = q*q, sk = k*k, sku = ku*ku;
#pragma unroll
    for (int o = 16; o > 0; o >>= 1) {
        sq  += __shfl_xor_sync(0xffffffffu, sq,  o);
        sk  += __shfl_xor_sync(0xffffffffu, sk,  o);
        sku += __shfl_xor_sync(0xffffffffu, sku, o);
    }
    q  *= rsqrtf(sq  + EPSF);
    k  *= rsqrtf(sk  + EPSF);
    ku *= rsqrtf(sku + EPSF);

    float dk = ku * k;
#pragma unroll
    for (int o = 16; o > 0; o >>= 1) dk += __shfl_xor_sync(0xffffffffu, dk, o);

    int base = w * 32;
    g_qn[base + lane]  = q;
    g_kn[base + lane]  = k;
    g_kun[base + lane] = ku;
    g_vu[base + lane]  = vur;
    if (lane == 0) {
        float br = g_ba[bs * 16 + h];
        float ar = g_ba[bs * 16 + 8 + h];
        float m  = mask[bs];
        g_sc[w*4 + 0] = sigm(br);                 // beta
        g_sc[w*4 + 1] = sigm(ar) * (1.f - m);     // Aeff
        g_sc[w*4 + 2] = sigm(gr);                 // Bg
        g_sc[w*4 + 3] = dk;                       // ku . k
    }
}

// ---------------- 5. phase 1: chunked scan, smem-broadcast operands ---------
__global__ __launch_bounds__(128) void phase1() {
    __shared__ float sk[4][32], sq[4][32], sku[4][32];
    int wq = threadIdx.x >> 5;
    int wg = blockIdx.x * 4 + wq;                   // 0..1023
    int lane = threadIdx.x & 31;
    int chain = wg >> 5;        // b*8+h
    int c = wg & 31;
    int b = chain >> 3, h = chain & 7;

    float cum[32], hl[32];
#pragma unroll
    for (int j = 0; j < 32; j++) { cum[j] = (j == lane) ? 1.f : 0.f; hl[j] = 0.f; }

    int t0 = c * CHUNK;
    int bs0 = b * NS + t0;
    int base = (bs0 * NH + h) * 32;
    float kreg  = g_kn[base + lane];
    float qreg  = g_qn[base + lane];
    float kureg = g_kun[base + lane];
    float vs    = g_proj[bs0 * NP1 + 512 + h * 32 + lane];
    float vu    = g_vu[base + lane];
    float4 scv  = *(const float4*)&g_sc[(bs0 * NH + h) * 4];

    for (int t = t0; t < t0 + CHUNK; t++) {
        __syncwarp();
        sk[wq][lane]  = kreg;
        sq[wq][lane]  = qreg;
        sku[wq][lane] = kureg;
        __syncwarp();

        // prefetch next timestep
        float kN = 0.f, qN = 0.f, kuN = 0.f, vsN = 0.f, vuN = 0.f;
        float4 scN = scv;
        int base2 = base;
        if (t + 1 < t0 + CHUNK) {
            int bs2 = b * NS + t + 1;
            int w2 = bs2 * NH + h;
            base2 = w2 * 32;
            kN  = g_kn[base2 + lane];
            qN  = g_qn[base2 + lane];
            kuN = g_kun[base2 + lane];
            vsN = g_proj[bs2 * NP1 + 512 + h * 32 + lane];
            vuN = g_vu[base2 + lane];
            scN = *(const float4*)&g_sc[w2 * 4];
        }

        float beta = scv.x, Ae = scv.y, Bg = scv.z, kuk = scv.w;
        float ck = 0.f, hk = 0.f;
#pragma unroll
        for (int j4 = 0; j4 < 8; j4++) {
            float4 k4 = *(const float4*)&sk[wq][j4 * 4];
            ck += cum[j4*4+0]*k4.x + cum[j4*4+1]*k4.y + cum[j4*4+2]*k4.z + cum[j4*4+3]*k4.w;
            hk += hl[j4*4+0]*k4.x  + hl[j4*4+1]*k4.y  + hl[j4*4+2]*k4.z  + hl[j4*4+3]*k4.w;
        }
        float e  = Ae * beta * ck;
        float cc = beta * vs - Ae * beta * hk - Bg * beta * kuk * vu;
        float dd = Bg * vu;

        float u = 0.f, wv = 0.f;
#pragma unroll
        for (int j4 = 0; j4 < 8; j4++) {
            float4 k4  = *(const float4*)&sk[wq][j4 * 4];
            float4 ku4 = *(const float4*)&sku[wq][j4 * 4];
            float4 q4  = *(const float4*)&sq[wq][j4 * 4];
            int j = j4 * 4;
            cum[j+0] = Ae * cum[j+0] - e * k4.x;
            cum[j+1] = Ae * cum[j+1] - e * k4.y;
            cum[j+2] = Ae * cum[j+2] - e * k4.z;
            cum[j+3] = Ae * cum[j+3] - e * k4.w;
            hl[j+0] = Ae * hl[j+0] + cc * k4.x + dd * ku4.x;
            hl[j+1] = Ae * hl[j+1] + cc * k4.y + dd * ku4.y;
            hl[j+2] = Ae * hl[j+2] + cc * k4.z + dd * ku4.z;
            hl[j+3] = Ae * hl[j+3] + cc * k4.w + dd * ku4.w;
            u  += cum[j+0]*q4.x + cum[j+1]*q4.y + cum[j+2]*q4.z + cum[j+3]*q4.w;
            wv += hl[j+0]*q4.x  + hl[j+1]*q4.y  + hl[j+2]*q4.z  + hl[j+3]*q4.w;
        }
        g_u[base + lane] = u;
        g_w[base + lane] = wv;

        kreg = kN; qreg = qN; kureg = kuN; vs = vsN; vu = vuN; scv = scN;
        base = base2;
    }
    int mb = (chain * NC + c) * 1024 + lane * 32;
#pragma unroll
    for (int j = 0; j < 32; j += 4) {
        *(float4*)&g_cum[mb + j] = make_float4(cum[j], cum[j+1], cum[j+2], cum[j+3]);
        *(float4*)&g_loc[mb + j] = make_float4(hl[j],  hl[j+1],  hl[j+2],  hl[j+3]);
    }
}

// ---------------- 6. phase 2: fold chunks (smem-staged, prefetched) ---------
__global__ __launch_bounds__(1024) void phase2(const float* __restrict__ carry,
                                               float* __restrict__ outCarry) {
    __shared__ float cumS[2][1024];
    int chain = blockIdx.x;
    int tid = threadIdx.x;
    int j = tid & 31;
    float hreg = carry[chain * 1024 + tid];

    int mb0 = (chain * NC) * 1024;
    float cumNext = g_cum[mb0 + tid];
    float locNext = g_loc[mb0 + tid];

    for (int c = 0; c < NC; c++) {
        int s = c & 1;
        cumS[s][tid] = cumNext;
        float locCur = locNext;
        __syncthreads();
        if (c + 1 < NC) {
            int mb1 = (chain * NC + c + 1) * 1024;
            cumNext = g_cum[mb1 + tid];
            locNext = g_loc[mb1 + tid];
        }
        g_hinit[(chain * NC + c) * 1024 + tid] = hreg;   // state at chunk start
        float nv = locCur;
#pragma unroll
        for (int m = 0; m < 32; m++)
            nv += __shfl_sync(0xffffffffu, hreg, m) * cumS[s][m * 32 + j];
        hreg = nv;
    }
    outCarry[chain * 1024 + tid] = hreg;  // new_carry
}

// --------- 7. fused phase3 + rms -> fp16: block per (b, chunk) ---------------
__global__ __launch_bounds__(512) void phase3_rms(const float* __restrict__ scale) {
    __shared__ float hin[NH][32 * 33];
    __shared__ float sscale[HID];
    __shared__ float partial[2][2][NH];
    int blk = blockIdx.x;            // b*NC + c
    int b = blk >> 5, c = blk & 31;
    int tid = threadIdx.x;
    int wid = tid >> 5, lane = tid & 31;
    int h = wid & 7, half = wid >> 3;

    for (int idx = tid; idx < NH * 1024; idx += 512) {
        int hh = idx >> 10, e = idx & 1023;
        int i = e >> 5, jj = e & 31;
        hin[hh][i * 33 + jj] = g_hinit[(((b * NH + hh) * NC) + c) * 1024 + e];
    }
    if (tid < HID) sscale[tid] = scale[tid];
    __syncthreads();

    for (int it = 0; it < 32; it++) {
        int t = c * CHUNK + half * 32 + it;
        int bsrow = b * NS + t;
        int base = (bsrow * NH + h) * 32;
        float ul  = g_u[base + lane];
        float acc = g_w[base + lane];
#pragma unroll
        for (int j = 0; j < 32; j++)
            acc += hin[h][lane * 33 + j] * __shfl_sync(0xffffffffu, ul, j);

        float ss = acc * acc;
#pragma unroll
        for (int o = 16; o > 0; o >>= 1) ss += __shfl_xor_sync(0xffffffffu, ss, o);
        int sBuf = it & 1;
        if (lane == 0) partial[half][sBuf][h] = ss;
        __syncthreads();
        float tot = partial[half][sBuf][0] + partial[half][sBuf][1]
                  + partial[half][sBuf][2] + partial[half][sBuf][3]
                  + partial[half][sBuf][4] + partial[half][sBuf][5]
                  + partial[half][sBuf][6] + partial[half][sBuf][7];
        float inv = rsqrtf(tot * (1.f / 256.f) + EPSF);
        float o = acc * inv * sscale[h * 32 + lane];
        g_o2h[bsrow * HID + h * 32 + lane] = __float2half_rn(o);
    }
}

// ---------------- launcher ---------------------------------------------------
extern "C" void kernel_launch(void* const* d_in, const int* in_sizes, int n_in,
                              void* d_out, int out_size) {
    const float* x      = (const float*)d_in[0];
    const float* action = (const float*)d_in[1];
    const float* mask   = (const float*)d_in[2];
    const float* carry  = (const float*)d_in[3];
    const float* Wq     = (const float*)d_in[4];
    const float* Wk     = (const float*)d_in[5];
    const float* Wv     = (const float*)d_in[6];
    const float* Wbeta  = (const float*)d_in[7];
    const float* Walpha = (const float*)d_in[8];
    const float* Wku    = (const float*)d_in[9];
    const float* Wvu    = (const float*)d_in[10];
    const float* Wgamma = (const float*)d_in[11];
    const float* rmssc  = (const float*)d_in[12];
    const float* Wout   = (const float*)d_in[13];
    const float* bout   = (const float*)d_in[14];

    float* outCarry = (float*)d_out;                       // (B,H,D,D) = 32768
    float* y        = (float*)d_out + NB * NH * ND * ND;   // (B,S,F)

    cudaFuncSetAttribute(gemm1_tc, cudaFuncAttributeMaxDynamicSharedMemorySize, SMEM_TOTAL);
    cudaFuncSetAttribute(gemm2_tc, cudaFuncAttributeMaxDynamicSharedMemorySize, SMEM_TOTAL);

    int nprep = N1ELEM + N2ELEM + N3ELEM;
    prep_weights<<<(nprep + 255) / 256, 256>>>(Wq, Wk, Wv, Wbeta, Walpha, Wout);
    split_x<<<(ROWS * NF / 4) / 256, 256>>>(x);
    balpha_kernel<<<ROWS / 8, 256>>>(x);

    dim3 g1(NP1 / 128, ROWS / 128);       // (6, 64)
    gemm1_tc<<<g1, 256, SMEM_TOTAL>>>();

    act_kernel<<<(ROWS * NH * 32) / 256, 256>>>(mask, action, Wku, Wvu, Wgamma);

    phase1<<<256, 128>>>();
    phase2<<<32, 1024>>>(carry, outCarry);
    phase3_rms<<<NB * NC, 512>>>(rmssc);

    dim3 g2(NF / 128, ROWS / 128);        // (4, 64)
    gemm2_tc<<<g2, 256, SMEM_TOTAL>>>(bout, y);
}

// round 10
// speedup vs baseline: 1.2381x; 1.0108x over previous
#include <cuda_runtime.h>
#include <cuda_fp16.h>
#include <cstdint>

// Problem constants
#define NB 4
#define NS 2048
#define NF 512
#define NH 8
#define ND 32
#define HID 256
#define ACTF 16
#define ROWS (NB*NS)          // 8192
#define NP1 768               // x-proj output width (q,k,v only)
#define NC 32                 // chunks per sequence
#define CHUNK 64              // NS / NC
#define EPSF 1e-6f
#define BSCALE 32.0f
#define BUNSCALE 0.03125f

// ---------------- scratch (static device globals; no allocations) ----------
__device__ __half g_Bt1h[NP1*NF];   // [768,512] W1^T hi (x32)
__device__ __half g_Bt1l[NP1*NF];   // lo
__device__ __half g_Bt2h[NF*HID];   // [512,256] Wout^T hi (x32)
__device__ __half g_Bt2l[NF*HID];
__device__ __half g_xh[ROWS*NF];    // x as fp16 (hi only)
__device__ __half g_o2h[ROWS*HID];  // rms output fp16 (GEMM2 A)
__device__ float g_WbaT[16*NF];     // transposed beta/alpha weights
__device__ float g_ba[ROWS*16];     // beta/alpha raw projections
__device__ float g_proj[ROWS*NP1];
__device__ float g_qn[ROWS*HID];
__device__ float g_kn[ROWS*HID];
__device__ float g_kun[ROWS*HID];
__device__ float g_vu[ROWS*HID];
__device__ float g_sc[ROWS*NH*4];   // beta, Aeff, Bg, ku.k
__device__ float g_u[ROWS*HID];
__device__ float g_w[ROWS*HID];
__device__ float g_cum[32*NC*ND*ND];
__device__ float g_loc[32*NC*ND*ND];
__device__ float g_hinit[32*NC*ND*ND];

__device__ __forceinline__ float sigm(float z) { return 1.f / (1.f + __expf(-z)); }

__device__ __forceinline__ uint32_t smem_to_u32(const void* smem_ptr) {
    uint32_t addr;
    asm("{ .reg .u64 tmp; cvta.to.shared.u64 tmp, %1; cvt.u32.u64 %0, tmp; }"
        : "=r"(addr) : "l"(smem_ptr));
    return addr;
}
__device__ __forceinline__ void ldsm_x4(uint32_t* r, uint32_t addr) {
    asm volatile("ldmatrix.sync.aligned.m8n8.x4.shared.b16 {%0,%1,%2,%3}, [%4];"
        : "=r"(r[0]), "=r"(r[1]), "=r"(r[2]), "=r"(r[3]) : "r"(addr));
}
__device__ __forceinline__ void mma16816(float* d, const uint32_t* a, const uint32_t* b) {
    asm volatile(
        "mma.sync.aligned.m16n8k16.row.col.f32.f16.f16.f32 "
        "{%0,%1,%2,%3}, {%4,%5,%6,%7}, {%8,%9}, {%0,%1,%2,%3};"
        : "+f"(d[0]), "+f"(d[1]), "+f"(d[2]), "+f"(d[3])
        : "r"(a[0]), "r"(a[1]), "r"(a[2]), "r"(a[3]), "r"(b[0]), "r"(b[1]));
}
__device__ __forceinline__ void cp16(uint32_t saddr, const void* gaddr) {
    asm volatile("cp.async.cg.shared.global [%0], [%1], 16;" :: "r"(saddr), "l"(gaddr));
}
__device__ __forceinline__ void cp_commit() {
    asm volatile("cp.async.commit_group;" ::: "memory");
}
__device__ __forceinline__ void cp_wait1() {
    asm volatile("cp.async.wait_group 1;" ::: "memory");
}

// ---------------- 1. weight prep ---------------------------------------------
#define N1ELEM (NP1*NF)
#define N2ELEM (NF*HID)
#define N3ELEM (16*NF)
__global__ void prep_weights(const float* __restrict__ Wq, const float* __restrict__ Wk,
                             const float* __restrict__ Wv, const float* __restrict__ Wb,
                             const float* __restrict__ Wa, const float* __restrict__ Wout) {
    int i = blockIdx.x * blockDim.x + threadIdx.x;
    if (i < N1ELEM) {
        int n = i >> 9, k = i & 511;          // Bt1[n,k] = W1[k,n] * 32
        float v;
        if (n < 256)       v = Wq[k*256 + n];
        else if (n < 512)  v = Wk[k*256 + n - 256];
        else               v = Wv[k*256 + n - 512];
        v *= BSCALE;
        __half h = __float2half_rn(v);
        g_Bt1h[i] = h;
        g_Bt1l[i] = __float2half_rn(v - __half2float(h));
    } else if (i < N1ELEM + N2ELEM) {
        int j = i - N1ELEM;
        int n = j >> 8, k = j & 255;          // Bt2[n,k] = Wout[k,n] * 32
        float v = Wout[k*512 + n] * BSCALE;
        __half h = __float2half_rn(v);
        g_Bt2h[j] = h;
        g_Bt2l[j] = __float2half_rn(v - __half2float(h));
    } else if (i < N1ELEM + N2ELEM + N3ELEM) {
        int j = i - N1ELEM - N2ELEM;
        int jj = j >> 9, k = j & 511;         // WbaT[jj][k]
        g_WbaT[j] = (jj < 8) ? Wb[k*8 + jj] : Wa[k*8 + (jj - 8)];
    }
}

// ---------------- 1b. x -> fp16 (hi only) -----------------------------------
__global__ __launch_bounds__(256) void split_x(const float* __restrict__ x) {
    int i = blockIdx.x * blockDim.x + threadIdx.x;   // float4 index
    float4 v = *(const float4*)(x + i * 4);
    __half2 p0 = __floats2half2_rn(v.x, v.y);
    __half2 p1 = __floats2half2_rn(v.z, v.w);
    uint2 hp;
    hp.x = *(uint32_t*)&p0;
    hp.y = *(uint32_t*)&p1;
    *(uint2*)(g_xh + i * 4) = hp;
}

// ---------------- 1c. beta/alpha: exact fp32 warp-per-row --------------------
__global__ __launch_bounds__(256) void balpha_kernel(const float* __restrict__ x) {
    int w = blockIdx.x * 8 + (threadIdx.x >> 5);     // bs row
    int lane = threadIdx.x & 31;
    const float* xr = x + (size_t)w * NF;
    float xreg[16];
#pragma unroll
    for (int i = 0; i < 16; i++) xreg[i] = xr[i * 32 + lane];
#pragma unroll
    for (int j = 0; j < 16; j++) {
        const float* wt = &g_WbaT[j * NF];
        float s = 0.f;
#pragma unroll
        for (int i = 0; i < 16; i++) s += xreg[i] * wt[i * 32 + lane];
#pragma unroll
        for (int o = 16; o > 0; o >>= 1) s += __shfl_xor_sync(0xffffffffu, s, o);
        if (lane == 0) g_ba[w * 16 + j] = s;
    }
}

// ---------------- 2. HMMA split-fp16 GEMM, 3-stage cp.async ------------------
// C = Ah(fp16) @ (Bh+Bl)(fp16,x32)^T * (1/32) (+bias). Tile 128x128, BK=32.
#define ROWB 80                 // padded smem row stride (bytes)
#define OAH 0
#define OBH 10240
#define OBL 20480
#define STG 30720
#define STAGES 3
#define SMEM_TOTAL (STAGES*STG)

__device__ __forceinline__ void gemm_hmma(const __half* __restrict__ Ah,
                                          const __half* __restrict__ Bh,
                                          const __half* __restrict__ Bl,
                                          float* __restrict__ C,
                                          const float* __restrict__ bias,
                                          int N, int K) {
    extern __shared__ char smem[];
    uint32_t sb = smem_to_u32(smem);
    int tid = threadIdx.x, lane = tid & 31, wid = tid >> 5;
    int m0 = blockIdx.y * 128, n0 = blockIdx.x * 128;
    int wm = (wid >> 2) * 64, wn = (wid & 3) * 32;

    uint32_t aOff = (uint32_t)((wm + (lane & 7) + ((lane >> 3) & 1) * 8) * ROWB
                               + ((lane >> 4) * 8) * 2);
    uint32_t bOff = (uint32_t)((wn + (lane & 7) + ((lane >> 4) & 1) * 8) * ROWB
                               + (((lane >> 3) & 1) * 8) * 2);

    float acc[4][4][4];
#pragma unroll
    for (int mt = 0; mt < 4; mt++)
#pragma unroll
        for (int nt = 0; nt < 4; nt++)
#pragma unroll
            for (int e = 0; e < 4; e++) acc[mt][nt][e] = 0.f;

    // copy mapping: thread t -> row = t>>1, 32B segment (t&1); 6 cp16/thread/stage
    int crow = tid >> 1;
    int cel = (tid & 1) * 16;
    uint32_t sOff = (uint32_t)(crow * ROWB + (tid & 1) * 32);
    const __half* pAh = Ah + (size_t)(m0 + crow) * K + cel;
    const __half* pBh = Bh + (size_t)(n0 + crow) * K + cel;
    const __half* pBl = Bl + (size_t)(n0 + crow) * K + cel;
    int nkc = K >> 5;

#define CP_STAGE(kc, s) do {                                            \
        uint32_t _stb = sb + (s) * STG;                                 \
        int _ko = (kc) * 32;                                            \
        cp16(_stb + OAH + sOff,      pAh + _ko);                        \
        cp16(_stb + OAH + sOff + 16, pAh + _ko + 8);                    \
        cp16(_stb + OBH + sOff,      pBh + _ko);                        \
        cp16(_stb + OBH + sOff + 16, pBh + _ko + 8);                    \
        cp16(_stb + OBL + sOff,      pBl + _ko);                        \
        cp16(_stb + OBL + sOff + 16, pBl + _ko + 8);                    \
    } while(0)

    // prologue: stages 0 and 1 in flight
    CP_STAGE(0, 0); cp_commit();
    CP_STAGE(1, 1); cp_commit();

    int s = 0;
    for (int kc = 0; kc < nkc; kc++) {
        cp_wait1();                 // stage kc landed (kc+1 may be in flight)
        __syncthreads();            // all warps done with stage (kc-1)%3

        int kn = kc + 2;
        if (kn < nkc) CP_STAGE(kn, (s + 2 >= STAGES) ? s + 2 - STAGES : s + 2);
        cp_commit();

        uint32_t stb = sb + s * STG;
#pragma unroll
        for (int ks = 0; ks < 2; ks++) {
            uint32_t kb = ks * 32;
            uint32_t af[4][4], bhF[2][4], blF[2][4];
#pragma unroll
            for (int mt = 0; mt < 4; mt++)
                ldsm_x4(af[mt], stb + OAH + aOff + mt * (16 * ROWB) + kb);
#pragma unroll
            for (int np = 0; np < 2; np++) {
                ldsm_x4(bhF[np], stb + OBH + bOff + np * (16 * ROWB) + kb);
                ldsm_x4(blF[np], stb + OBL + bOff + np * (16 * ROWB) + kb);
            }
#pragma unroll
            for (int mt = 0; mt < 4; mt++)
#pragma unroll
                for (int nt = 0; nt < 4; nt++)
                    mma16816(acc[mt][nt], af[mt], &bhF[nt >> 1][(nt & 1) * 2]);
#pragma unroll
            for (int mt = 0; mt < 4; mt++)
#pragma unroll
                for (int nt = 0; nt < 4; nt++)
                    mma16816(acc[mt][nt], af[mt], &blF[nt >> 1][(nt & 1) * 2]);
        }
        s = (s + 1 >= STAGES) ? 0 : s + 1;
    }
#undef CP_STAGE

    // epilogue: unscale by 1/32, then optional bias
#pragma unroll
    for (int mt = 0; mt < 4; mt++) {
        int r0 = m0 + wm + mt * 16 + (lane >> 2);
#pragma unroll
        for (int nt = 0; nt < 4; nt++) {
            int col = n0 + wn + nt * 8 + (lane & 3) * 2;
            float b0 = 0.f, b1 = 0.f;
            if (bias) { b0 = bias[col]; b1 = bias[col + 1]; }
            float2 v0, v1;
            v0.x = acc[mt][nt][0] * BUNSCALE + b0; v0.y = acc[mt][nt][1] * BUNSCALE + b1;
            v1.x = acc[mt][nt][2] * BUNSCALE + b0; v1.y = acc[mt][nt][3] * BUNSCALE + b1;
            *(float2*)(C + (size_t)r0 * N + col) = v0;
            *(float2*)(C + (size_t)(r0 + 8) * N + col) = v1;
        }
    }
}

__global__ __launch_bounds__(256, 2) void gemm1_tc() {
    gemm_hmma(g_xh, g_Bt1h, g_Bt1l, g_proj, nullptr, NP1, NF);
}
__global__ __launch_bounds__(256, 2) void gemm2_tc(const float* __restrict__ bout,
                                                   float* __restrict__ y) {
    gemm_hmma(g_o2h, g_Bt2h, g_Bt2l, y, bout, NF, HID);
}

// ------- 3. activations + l2norm + fused action proj (coalesced weights) ----
__global__ __launch_bounds__(256) void act_kernel(const float* __restrict__ mask,
                                                  const float* __restrict__ action,
                                                  const float* __restrict__ Wku,
                                                  const float* __restrict__ Wvu,
                                                  const float* __restrict__ Wg) {
    int w = (blockIdx.x * blockDim.x + threadIdx.x) >> 5;   // (b*S+s)*H + h
    int lane = threadIdx.x & 31;
    if (w >= ROWS * NH) return;
    int bs = w >> 3, h = w & 7;
    int pb = bs * NP1;

    // action row: 4 broadcast float4 loads
    const float4* ar4 = (const float4*)(action + bs * ACTF);
    float4 a0 = ar4[0], a1 = ar4[1], a2 = ar4[2], a3 = ar4[3];
    float a[ACTF] = { a0.x,a0.y,a0.z,a0.w, a1.x,a1.y,a1.z,a1.w,
                      a2.x,a2.y,a2.z,a2.w, a3.x,a3.y,a3.z,a3.w };

    int c = h * 32 + lane;
    float kur = 0.f, vur = 0.f, gr = 0.f;
#pragma unroll
    for (int k2 = 0; k2 < ACTF; k2++) {
        kur += a[k2] * Wku[k2 * HID + c];
        vur += a[k2] * Wvu[k2 * HID + c];
        gr  += a[k2] * Wg[k2 * NH + h];
    }

    float qr  = g_proj[pb + h*32 + lane];
    float kr  = g_proj[pb + 256 + h*32 + lane];

    float q  = qr * sigm(qr);
    float k  = kr * sigm(kr);
    float ku = kur * sigm(kur);

    float sq = q*q, sk = k*k, sku = ku*ku;
#pragma unroll
    for (int o = 16; o > 0; o >>= 1) {
        sq  += __shfl_xor_sync(0xffffffffu, sq,  o);
        sk  += __shfl_xor_sync(0xffffffffu, sk,  o);
        sku += __shfl_xor_sync(0xffffffffu, sku, o);
    }
    q  *= rsqrtf(sq  + EPSF);
    k  *= rsqrtf(sk  + EPSF);
    ku *= rsqrtf(sku + EPSF);

    float dk = ku * k;
#pragma unroll
    for (int o = 16; o > 0; o >>= 1) dk += __shfl_xor_sync(0xffffffffu, dk, o);

    int base = w * 32;
    g_qn[base + lane]  = q;
    g_kn[base + lane]  = k;
    g_kun[base + lane] = ku;
    g_vu[base + lane]  = vur;
    if (lane == 0) {
        float br = g_ba[bs * 16 + h];
        float ar = g_ba[bs * 16 + 8 + h];
        float m  = mask[bs];
        g_sc[w*4 + 0] = sigm(br);                 // beta
        g_sc[w*4 + 1] = sigm(ar) * (1.f - m);     // Aeff
        g_sc[w*4 + 2] = sigm(gr);                 // Bg
        g_sc[w*4 + 3] = dk;                       // ku . k
    }
}

// ---------------- 5. phase 1: chunked scan, smem-broadcast operands ---------
__global__ __launch_bounds__(128) void phase1() {
    __shared__ float sk[4][32], sq[4][32], sku[4][32];
    int wq = threadIdx.x >> 5;
    int wg = blockIdx.x * 4 + wq;                   // 0..1023
    int lane = threadIdx.x & 31;
    int chain = wg >> 5;        // b*8+h
    int c = wg & 31;
    int b = chain >> 3, h = chain & 7;

    float cum[32], hl[32];
#pragma unroll
    for (int j = 0; j < 32; j++) { cum[j] = (j == lane) ? 1.f : 0.f; hl[j] = 0.f; }

    int t0 = c * CHUNK;
    int bs0 = b * NS + t0;
    int base = (bs0 * NH + h) * 32;
    float kreg  = g_kn[base + lane];
    float qreg  = g_qn[base + lane];
    float kureg = g_kun[base + lane];
    float vs    = g_proj[bs0 * NP1 + 512 + h * 32 + lane];
    float vu    = g_vu[base + lane];
    float4 scv  = *(const float4*)&g_sc[(bs0 * NH + h) * 4];

    for (int t = t0; t < t0 + CHUNK; t++) {
        __syncwarp();
        sk[wq][lane]  = kreg;
        sq[wq][lane]  = qreg;
        sku[wq][lane] = kureg;
        __syncwarp();

        // prefetch next timestep
        float kN = 0.f, qN = 0.f, kuN = 0.f, vsN = 0.f, vuN = 0.f;
        float4 scN = scv;
        int base2 = base;
        if (t + 1 < t0 + CHUNK) {
            int bs2 = b * NS + t + 1;
            int w2 = bs2 * NH + h;
            base2 = w2 * 32;
            kN  = g_kn[base2 + lane];
            qN  = g_qn[base2 + lane];
            kuN = g_kun[base2 + lane];
            vsN = g_proj[bs2 * NP1 + 512 + h * 32 + lane];
            vuN = g_vu[base2 + lane];
            scN = *(const float4*)&g_sc[w2 * 4];
        }

        float beta = scv.x, Ae = scv.y, Bg = scv.z, kuk = scv.w;
        float ck = 0.f, hk = 0.f;
#pragma unroll
        for (int j4 = 0; j4 < 8; j4++) {
            float4 k4 = *(const float4*)&sk[wq][j4 * 4];
            ck += cum[j4*4+0]*k4.x + cum[j4*4+1]*k4.y + cum[j4*4+2]*k4.z + cum[j4*4+3]*k4.w;
            hk += hl[j4*4+0]*k4.x  + hl[j4*4+1]*k4.y  + hl[j4*4+2]*k4.z  + hl[j4*4+3]*k4.w;
        }
        float e  = Ae * beta * ck;
        float cc = beta * vs - Ae * beta * hk - Bg * beta * kuk * vu;
        float dd = Bg * vu;

        float u = 0.f, wv = 0.f;
#pragma unroll
        for (int j4 = 0; j4 < 8; j4++) {
            float4 k4  = *(const float4*)&sk[wq][j4 * 4];
            float4 ku4 = *(const float4*)&sku[wq][j4 * 4];
            float4 q4  = *(const float4*)&sq[wq][j4 * 4];
            int j = j4 * 4;
            cum[j+0] = Ae * cum[j+0] - e * k4.x;
            cum[j+1] = Ae * cum[j+1] - e * k4.y;
            cum[j+2] = Ae * cum[j+2] - e * k4.z;
            cum[j+3] = Ae * cum[j+3] - e * k4.w;
            hl[j+0] = Ae * hl[j+0] + cc * k4.x + dd * ku4.x;
            hl[j+1] = Ae * hl[j+1] + cc * k4.y + dd * ku4.y;
            hl[j+2] = Ae * hl[j+2] + cc * k4.z + dd * ku4.z;
            hl[j+3] = Ae * hl[j+3] + cc * k4.w + dd * ku4.w;
            u  += cum[j+0]*q4.x + cum[j+1]*q4.y + cum[j+2]*q4.z + cum[j+3]*q4.w;
            wv += hl[j+0]*q4.x  + hl[j+1]*q4.y  + hl[j+2]*q4.z  + hl[j+3]*q4.w;
        }
        g_u[base + lane] = u;
        g_w[base + lane] = wv;

        kreg = kN; qreg = qN; kureg = kuN; vs = vsN; vu = vuN; scv = scN;
        base = base2;
    }
    int mb = (chain * NC + c) * 1024 + lane * 32;
#pragma unroll
    for (int j = 0; j < 32; j += 4) {
        *(float4*)&g_cum[mb + j] = make_float4(cum[j], cum[j+1], cum[j+2], cum[j+3]);
        *(float4*)&g_loc[mb + j] = make_float4(hl[j],  hl[j+1],  hl[j+2],  hl[j+3]);
    }
}

// ---------------- 6. phase 2: fold chunks (smem-staged, prefetched) ---------
__global__ __launch_bounds__(1024) void phase2(const float* __restrict__ carry,
                                               float* __restrict__ outCarry) {
    __shared__ float cumS[2][1024];
    int chain = blockIdx.x;
    int tid = threadIdx.x;
    int j = tid & 31;
    float hreg = carry[chain * 1024 + tid];

    int mb0 = (chain * NC) * 1024;
    float cumNext = g_cum[mb0 + tid];
    float locNext = g_loc[mb0 + tid];

    for (int c = 0; c < NC; c++) {
        int s = c & 1;
        cumS[s][tid] = cumNext;
        float locCur = locNext;
        __syncthreads();
        if (c + 1 < NC) {
            int mb1 = (chain * NC + c + 1) * 1024;
            cumNext = g_cum[mb1 + tid];
            locNext = g_loc[mb1 + tid];
        }
        g_hinit[(chain * NC + c) * 1024 + tid] = hreg;   // state at chunk start
        float nv = locCur;
#pragma unroll
        for (int m = 0; m < 32; m++)
            nv += __shfl_sync(0xffffffffu, hreg, m) * cumS[s][m * 32 + j];
        hreg = nv;
    }
    outCarry[chain * 1024 + tid] = hreg;  // new_carry
}

// --------- 7. fused phase3 + rms -> fp16: block per (b, chunk) ---------------
__global__ __launch_bounds__(512) void phase3_rms(const float* __restrict__ scale) {
    __shared__ float hin[NH][32 * 33];
    __shared__ float sscale[HID];
    __shared__ float partial[2][2][NH];
    int blk = blockIdx.x;            // b*NC + c
    int b = blk >> 5, c = blk & 31;
    int tid = threadIdx.x;
    int wid = tid >> 5, lane = tid & 31;
    int h = wid & 7, half = wid >> 3;

    for (int idx = tid; idx < NH * 1024; idx += 512) {
        int hh = idx >> 10, e = idx & 1023;
        int i = e >> 5, jj = e & 31;
        hin[hh][i * 33 + jj] = g_hinit[(((b * NH + hh) * NC) + c) * 1024 + e];
    }
    if (tid < HID) sscale[tid] = scale[tid];
    __syncthreads();

    for (int it = 0; it < 32; it++) {
        int t = c * CHUNK + half * 32 + it;
        int bsrow = b * NS + t;
        int base = (bsrow * NH + h) * 32;
        float ul  = g_u[base + lane];
        float acc = g_w[base + lane];
#pragma unroll
        for (int j = 0; j < 32; j++)
            acc += hin[h][lane * 33 + j] * __shfl_sync(0xffffffffu, ul, j);

        float ss = acc * acc;
#pragma unroll
        for (int o = 16; o > 0; o >>= 1) ss += __shfl_xor_sync(0xffffffffu, ss, o);
        int sBuf = it & 1;
        if (lane == 0) partial[half][sBuf][h] = ss;
        __syncthreads();
        float tot = partial[half][sBuf][0] + partial[half][sBuf][1]
                  + partial[half][sBuf][2] + partial[half][sBuf][3]
                  + partial[half][sBuf][4] + partial[half][sBuf][5]
                  + partial[half][sBuf][6] + partial[half][sBuf][7];
        float inv = rsqrtf(tot * (1.f / 256.f) + EPSF);
        float o = acc * inv * sscale[h * 32 + lane];
        g_o2h[bsrow * HID + h * 32 + lane] = __float2half_rn(o);
    }
}

// ---------------- launcher ---------------------------------------------------
extern "C" void kernel_launch(void* const* d_in, const int* in_sizes, int n_in,
                              void* d_out, int out_size) {
    const float* x      = (const float*)d_in[0];
    const float* action = (const float*)d_in[1];
    const float* mask   = (const float*)d_in[2];
    const float* carry  = (const float*)d_in[3];
    const float* Wq     = (const float*)d_in[4];
    const float* Wk     = (const float*)d_in[5];
    const float* Wv     = (const float*)d_in[6];
    const float* Wbeta  = (const float*)d_in[7];
    const float* Walpha = (const float*)d_in[8];
    const float* Wku    = (const float*)d_in[9];
    const float* Wvu    = (const float*)d_in[10];
    const float* Wgamma = (const float*)d_in[11];
    const float* rmssc  = (const float*)d_in[12];
    const float* Wout   = (const float*)d_in[13];
    const float* bout   = (const float*)d_in[14];

    float* outCarry = (float*)d_out;                       // (B,H,D,D) = 32768
    float* y        = (float*)d_out + NB * NH * ND * ND;   // (B,S,F)

    cudaFuncSetAttribute(gemm1_tc, cudaFuncAttributeMaxDynamicSharedMemorySize, SMEM_TOTAL);
    cudaFuncSetAttribute(gemm2_tc, cudaFuncAttributeMaxDynamicSharedMemorySize, SMEM_TOTAL);

    int nprep = N1ELEM + N2ELEM + N3ELEM;
    prep_weights<<<(nprep + 255) / 256, 256>>>(Wq, Wk, Wv, Wbeta, Walpha, Wout);
    split_x<<<(ROWS * NF / 4) / 256, 256>>>(x);
    balpha_kernel<<<ROWS / 8, 256>>>(x);

    dim3 g1(NP1 / 128, ROWS / 128);       // (6, 64)
    gemm1_tc<<<g1, 256, SMEM_TOTAL>>>();

    act_kernel<<<(ROWS * NH * 32) / 256, 256>>>(mask, action, Wku, Wvu, Wgamma);

    phase1<<<256, 128>>>();
    phase2<<<32, 1024>>>(carry, outCarry);
    phase3_rms<<<NB * NC, 512>>>(rmssc);

    dim3 g2(NF / 128, ROWS / 128);        // (4, 64)
    gemm2_tc<<<g2, 256, SMEM_TOTAL>>>(bout, y);
}